// round 4
// baseline (speedup 1.0000x reference)
#include <cuda_runtime.h>
#include <math.h>

#define NB 4
#define NH 16
#define TT 2048
#define DH 64
#define CC 1024
#define MROWS (NB*TT)   // 8192

// Scratch (allocation-free rule: __device__ globals)
__device__ float g_q[NB*NH*TT*DH];   // [B,H,T,D]
__device__ float g_k[NB*NH*TT*DH];
__device__ float g_v[NB*NH*TT*DH];
__device__ float g_y[MROWS*CC];      // [B,T,C] attention output

// ---------------------------------------------------------------------------
// SGEMM: C[M,N] = A[M,K] @ B[K,N] + bias[N]
// MODE 0: A = x, epilogue scatters into g_q/g_k/g_v in [B,H,T,D] layout
// MODE 1: A = g_y, epilogue writes Out directly (proj)
// 128x128 tile, BK=8, 256 threads, 8x8 per-thread register block.
// ---------------------------------------------------------------------------
template<int MODE>
__global__ __launch_bounds__(256)
void sgemm_kernel(const float* __restrict__ Ain,
                  const float* __restrict__ B,
                  const float* __restrict__ bias,
                  float* __restrict__ Out,
                  int N, int K)
{
    const float* A = (MODE == 1) ? (const float*)g_y : Ain;
    constexpr int BM = 128, BN = 128, BK = 8;
    __shared__ float As[BK][BM];   // transposed A tile
    __shared__ float Bs[BK][BN];

    const int tid  = threadIdx.x;
    const int row0 = blockIdx.y * BM;
    const int col0 = blockIdx.x * BN;

    const int aRow = tid >> 1;            // 0..127
    const int aCol = (tid & 1) << 2;      // 0 or 4
    const int bRow = tid >> 5;            // 0..7
    const int bCol = (tid & 31) << 2;     // 0..124

    const float* Ap = A + (size_t)(row0 + aRow) * K + aCol;
    const float* Bp = B + (size_t)bRow * N + col0 + bCol;

    const int tr = tid >> 4;   // 0..15 -> rows tr*8..tr*8+7
    const int tc = tid & 15;   // 0..15 -> cols tc*8..tc*8+7

    float acc[8][8];
    #pragma unroll
    for (int i = 0; i < 8; i++)
        #pragma unroll
        for (int j = 0; j < 8; j++) acc[i][j] = 0.f;

    float4 av = *(const float4*)Ap;
    float4 bv = *(const float4*)Bp;

    for (int k0 = 0; k0 < K; k0 += BK) {
        As[aCol + 0][aRow] = av.x;
        As[aCol + 1][aRow] = av.y;
        As[aCol + 2][aRow] = av.z;
        As[aCol + 3][aRow] = av.w;
        *(float4*)&Bs[bRow][bCol] = bv;
        __syncthreads();

        if (k0 + BK < K) {   // register prefetch of next K-tile
            av = *(const float4*)(Ap + k0 + BK);
            bv = *(const float4*)(Bp + (size_t)(k0 + BK) * N);
        }

        #pragma unroll
        for (int kk = 0; kk < BK; kk++) {
            float a[8], b[8];
            *(float4*)(a + 0) = *(const float4*)&As[kk][tr*8 + 0];
            *(float4*)(a + 4) = *(const float4*)&As[kk][tr*8 + 4];
            *(float4*)(b + 0) = *(const float4*)&Bs[kk][tc*8 + 0];
            *(float4*)(b + 4) = *(const float4*)&Bs[kk][tc*8 + 4];
            #pragma unroll
            for (int i = 0; i < 8; i++)
                #pragma unroll
                for (int j = 0; j < 8; j++)
                    acc[i][j] = fmaf(a[i], b[j], acc[i][j]);
        }
        __syncthreads();
    }

    const int cb = col0 + tc*8;   // 8-aligned, never straddles 64/1024 boundaries
    float4 bias0 = *(const float4*)(bias + cb);
    float4 bias1 = *(const float4*)(bias + cb + 4);

    if (MODE == 0) {
        const int which = cb >> 10;          // 0=q 1=k 2=v
        const int rem   = cb & (CC - 1);
        const int h     = rem >> 6;
        const int d0    = rem & (DH - 1);
        float* dstbase = (which == 0) ? g_q : (which == 1) ? g_k : g_v;
        #pragma unroll
        for (int i = 0; i < 8; i++) {
            const int grow = row0 + tr*8 + i;
            const int bb = grow >> 11;           // T = 2048
            const int t  = grow & (TT - 1);
            float* dp = dstbase + ((size_t)(bb*NH + h)*TT + t)*DH + d0;
            float4 r0, r1;
            r0.x = acc[i][0] + bias0.x; r0.y = acc[i][1] + bias0.y;
            r0.z = acc[i][2] + bias0.z; r0.w = acc[i][3] + bias0.w;
            r1.x = acc[i][4] + bias1.x; r1.y = acc[i][5] + bias1.y;
            r1.z = acc[i][6] + bias1.z; r1.w = acc[i][7] + bias1.w;
            *(float4*)(dp + 0) = r0;
            *(float4*)(dp + 4) = r1;
        }
    } else {
        #pragma unroll
        for (int i = 0; i < 8; i++) {
            const int grow = row0 + tr*8 + i;
            float* op = Out + (size_t)grow * N + cb;
            float4 r0, r1;
            r0.x = acc[i][0] + bias0.x; r0.y = acc[i][1] + bias0.y;
            r0.z = acc[i][2] + bias0.z; r0.w = acc[i][3] + bias0.w;
            r1.x = acc[i][4] + bias1.x; r1.y = acc[i][5] + bias1.y;
            r1.z = acc[i][6] + bias1.z; r1.w = acc[i][7] + bias1.w;
            *(float4*)(op + 0) = r0;
            *(float4*)(op + 4) = r1;
        }
    }
}

// ---------------------------------------------------------------------------
// Flash attention, causal, fp32. One CTA = 64 query rows of one (b,h).
// 256 threads: tr=tid/16 owns rows {tr+16i}, tc=tid%16 owns cols {tc+16j}.
// Row-wise softmax reductions are half-warp shuffles (width 16).
// ---------------------------------------------------------------------------
#define FLASH_SMEM_FLOATS (64*64 + 64*65 + 64*64 + 64*64)
#define FLASH_SMEM_BYTES  (FLASH_SMEM_FLOATS * 4)

__global__ __launch_bounds__(256)
void flash_kernel()
{
    extern __shared__ float sm[];
    float* Qs = sm;              // [64][64]
    float* Ks = Qs + 64*64;      // [64][65]  padded: conflict-free K^T reads
    float* Vs = Ks + 64*65;      // [64][64]
    float* Ps = Vs + 64*64;      // [64][64]

    const int qt = (int)gridDim.x - 1 - (int)blockIdx.x;  // heavy tiles first
    const int bh = blockIdx.y;
    const float* Qg = g_q + (size_t)bh * TT * DH + (size_t)qt * 64 * DH;
    const float* Kg = g_k + (size_t)bh * TT * DH;
    const float* Vg = g_v + (size_t)bh * TT * DH;

    const int tid = threadIdx.x;
    const int tr = tid >> 4;
    const int tc = tid & 15;

    // Load Q tile
    #pragma unroll
    for (int u = 0; u < 4; u++) {
        int idx4 = tid + 256*u;          // 1024 float4s
        int r = idx4 >> 4;
        int c = (idx4 & 15) << 2;
        *(float4*)&Qs[r*64 + c] = *(const float4*)(Qg + r*DH + c);
    }

    float m[4], l[4], o[4][4];
    #pragma unroll
    for (int i = 0; i < 4; i++) {
        m[i] = -INFINITY; l[i] = 0.f;
        #pragma unroll
        for (int j = 0; j < 4; j++) o[i][j] = 0.f;
    }

    for (int jc = 0; jc <= qt; jc++) {
        __syncthreads();   // prev iter's smem reads done (also covers Q store)
        #pragma unroll
        for (int u = 0; u < 4; u++) {
            int idx4 = tid + 256*u;
            int r = idx4 >> 4;
            int c = (idx4 & 15) << 2;
            float4 kv = *(const float4*)(Kg + (size_t)(jc*64 + r)*DH + c);
            Ks[r*65 + c + 0] = kv.x;
            Ks[r*65 + c + 1] = kv.y;
            Ks[r*65 + c + 2] = kv.z;
            Ks[r*65 + c + 3] = kv.w;
            *(float4*)&Vs[r*64 + c] = *(const float4*)(Vg + (size_t)(jc*64 + r)*DH + c);
        }
        __syncthreads();

        // S = Q @ K^T (per-thread 4x4)
        float s[4][4];
        #pragma unroll
        for (int i = 0; i < 4; i++)
            #pragma unroll
            for (int j = 0; j < 4; j++) s[i][j] = 0.f;

        #pragma unroll 4
        for (int kk = 0; kk < 64; kk++) {
            float qv[4], kv[4];
            #pragma unroll
            for (int i = 0; i < 4; i++) qv[i] = Qs[(tr + 16*i)*64 + kk];
            #pragma unroll
            for (int j = 0; j < 4; j++) kv[j] = Ks[(tc + 16*j)*65 + kk];
            #pragma unroll
            for (int i = 0; i < 4; i++)
                #pragma unroll
                for (int j = 0; j < 4; j++)
                    s[i][j] = fmaf(qv[i], kv[j], s[i][j]);
        }

        // scale + causal mask (diagonal tile only)
        const bool diag = (jc == qt);
        #pragma unroll
        for (int i = 0; i < 4; i++)
            #pragma unroll
            for (int j = 0; j < 4; j++) {
                s[i][j] *= 0.125f;   // 1/sqrt(64)
                if (diag && (tc + 16*j) > (tr + 16*i)) s[i][j] = -INFINITY;
            }

        // online softmax update
        #pragma unroll
        for (int i = 0; i < 4; i++) {
            float v = fmaxf(fmaxf(s[i][0], s[i][1]), fmaxf(s[i][2], s[i][3]));
            #pragma unroll
            for (int off = 8; off >= 1; off >>= 1)
                v = fmaxf(v, __shfl_xor_sync(0xffffffffu, v, off, 16));
            const float mn = fmaxf(m[i], v);      // finite after first tile
            const float alpha = __expf(m[i] - mn);
            float ps = 0.f;
            #pragma unroll
            for (int j = 0; j < 4; j++) {
                const float p = __expf(s[i][j] - mn);
                s[i][j] = p;
                ps += p;
            }
            #pragma unroll
            for (int off = 8; off >= 1; off >>= 1)
                ps += __shfl_xor_sync(0xffffffffu, ps, off, 16);
            l[i] = l[i]*alpha + ps;
            m[i] = mn;
            #pragma unroll
            for (int j = 0; j < 4; j++) {
                o[i][j] *= alpha;
                Ps[(tr + 16*i)*64 + tc + 16*j] = s[i][j];
            }
        }
        // P rows are produced/consumed within the same half-warp group
        __syncwarp();

        // O += P @ V
        #pragma unroll 4
        for (int kk = 0; kk < 64; kk++) {
            float pv[4], vv[4];
            #pragma unroll
            for (int i = 0; i < 4; i++) pv[i] = Ps[(tr + 16*i)*64 + kk];
            #pragma unroll
            for (int j = 0; j < 4; j++) vv[j] = Vs[kk*64 + tc + 16*j];
            #pragma unroll
            for (int i = 0; i < 4; i++)
                #pragma unroll
                for (int j = 0; j < 4; j++)
                    o[i][j] = fmaf(pv[i], vv[j], o[i][j]);
        }
    }

    // normalize + write y in [B,T,C] layout
    const int bb = bh >> 4;
    const int h  = bh & (NH - 1);
    #pragma unroll
    for (int i = 0; i < 4; i++) {
        const float inv = 1.0f / l[i];
        const int row = qt*64 + tr + 16*i;
        float* yp = g_y + ((size_t)bb*TT + row)*CC + h*DH;
        #pragma unroll
        for (int j = 0; j < 4; j++)
            yp[tc + 16*j] = o[i][j] * inv;
    }
}

// ---------------------------------------------------------------------------
extern "C" void kernel_launch(void* const* d_in, const int* in_sizes, int n_in,
                              void* d_out, int out_size)
{
    (void)in_sizes; (void)n_in; (void)out_size;
    const float* x     = (const float*)d_in[0];
    const float* Wqkv  = (const float*)d_in[1];
    const float* bqkv  = (const float*)d_in[2];
    const float* Wproj = (const float*)d_in[3];
    const float* bproj = (const float*)d_in[4];
    float* out = (float*)d_out;

    // one-time, capture-safe (not a stream op, no allocation)
    static bool attr_set = false;
    if (!attr_set) {
        cudaFuncSetAttribute(flash_kernel,
            cudaFuncAttributeMaxDynamicSharedMemorySize, FLASH_SMEM_BYTES);
        attr_set = true;
    }

    // 1) QKV projection with scatter to [B,H,T,D]
    dim3 gq(3*CC/128, MROWS/128);   // (24, 64)
    sgemm_kernel<0><<<gq, 256>>>(x, Wqkv, bqkv, nullptr, 3*CC, CC);

    // 2) causal flash attention -> g_y [B,T,C]
    dim3 gf(TT/64, NB*NH);          // (32, 64)
    flash_kernel<<<gf, 256, FLASH_SMEM_BYTES>>>();

    // 3) output projection -> d_out
    dim3 gp(CC/128, MROWS/128);     // (8, 64)
    sgemm_kernel<1><<<gp, 256>>>(nullptr, Wproj, bproj, out, CC, CC);
}

// round 5
// speedup vs baseline: 1.0117x; 1.0117x over previous
#include <cuda_runtime.h>
#include <math.h>

#define NB 4
#define NH 16
#define TT 2048
#define DH 64
#define CC 1024
#define MROWS (NB*TT)   // 8192

// Scratch (allocation-free rule: __device__ globals)
__device__ float g_q[NB*NH*TT*DH];   // [B,H,T,D]
__device__ float g_k[NB*NH*TT*DH];
__device__ float g_v[NB*NH*TT*DH];
__device__ float g_y[MROWS*CC];      // [B,T,C] attention output

// ---------------------------------------------------------------------------
// Packed fp32x2 helpers (sm_103a FFMA2 path — only reachable via PTX)
// ---------------------------------------------------------------------------
typedef unsigned long long u64;

__device__ __forceinline__ u64 pk2(float lo, float hi) {
    u64 r;
    asm("mov.b64 %0, {%1, %2};" : "=l"(r) : "f"(lo), "f"(hi));
    return r;
}
__device__ __forceinline__ void upk2(float& lo, float& hi, u64 v) {
    asm("mov.b64 {%0, %1}, %2;" : "=f"(lo), "=f"(hi) : "l"(v));
}
__device__ __forceinline__ void fma2(u64& d, u64 a, u64 b) {
    asm("fma.rn.f32x2 %0, %1, %2, %0;" : "+l"(d) : "l"(a), "l"(b));
}
__device__ __forceinline__ void mul2(u64& d, u64 a) {
    asm("mul.rn.f32x2 %0, %0, %1;" : "+l"(d) : "l"(a));
}

// ---------------------------------------------------------------------------
// SGEMM: C[M,N] = A[M,K] @ B[K,N] + bias[N]   (packed f32x2 inner product)
// MODE 0: A = x, epilogue scatters into g_q/g_k/g_v in [B,H,T,D] layout
// MODE 1: A = g_y, epilogue writes Out directly (proj)
// 128x128 tile, BK=8, 256 threads, 8x8 per-thread register block.
// ---------------------------------------------------------------------------
template<int MODE>
__global__ __launch_bounds__(256)
void sgemm_kernel(const float* __restrict__ Ain,
                  const float* __restrict__ B,
                  const float* __restrict__ bias,
                  float* __restrict__ Out,
                  int N, int K)
{
    const float* A = (MODE == 1) ? (const float*)g_y : Ain;
    constexpr int BM = 128, BN = 128, BK = 8;
    __shared__ float As[BK][BM];   // transposed A tile
    __shared__ float Bs[BK][BN];

    const int tid  = threadIdx.x;
    const int row0 = blockIdx.y * BM;
    const int col0 = blockIdx.x * BN;

    const int aRow = tid >> 1;            // 0..127
    const int aCol = (tid & 1) << 2;      // 0 or 4
    const int bRow = tid >> 5;            // 0..7
    const int bCol = (tid & 31) << 2;     // 0..124

    const float* Ap = A + (size_t)(row0 + aRow) * K + aCol;
    const float* Bp = B + (size_t)bRow * N + col0 + bCol;

    const int tr = tid >> 4;   // 0..15 -> rows tr*8..tr*8+7
    const int tc = tid & 15;   // 0..15 -> cols tc*8..tc*8+7

    // packed accumulators: acc2[i][p] = C[row i][col 2p, 2p+1]
    u64 acc2[8][4];
    #pragma unroll
    for (int i = 0; i < 8; i++)
        #pragma unroll
        for (int p = 0; p < 4; p++) acc2[i][p] = 0ull;

    float4 av = *(const float4*)Ap;
    float4 bv = *(const float4*)Bp;

    for (int k0 = 0; k0 < K; k0 += BK) {
        As[aCol + 0][aRow] = av.x;
        As[aCol + 1][aRow] = av.y;
        As[aCol + 2][aRow] = av.z;
        As[aCol + 3][aRow] = av.w;
        *(float4*)&Bs[bRow][bCol] = bv;
        __syncthreads();

        if (k0 + BK < K) {   // register prefetch of next K-tile
            av = *(const float4*)(Ap + k0 + BK);
            bv = *(const float4*)(Bp + (size_t)(k0 + BK) * N);
        }

        #pragma unroll
        for (int kk = 0; kk < BK; kk++) {
            float a[8];
            *(float4*)(a + 0) = *(const float4*)&As[kk][tr*8 + 0];
            *(float4*)(a + 4) = *(const float4*)&As[kk][tr*8 + 4];
            // B pairs directly as 64-bit lanes (register-pair aliasing of LDS.128)
            ulonglong2 b01 = *(const ulonglong2*)&Bs[kk][tc*8 + 0];
            ulonglong2 b23 = *(const ulonglong2*)&Bs[kk][tc*8 + 4];
            u64 bb0 = b01.x, bb1 = b01.y, bb2 = b23.x, bb3 = b23.y;
            #pragma unroll
            for (int i = 0; i < 8; i++) {
                u64 ad = pk2(a[i], a[i]);
                fma2(acc2[i][0], ad, bb0);
                fma2(acc2[i][1], ad, bb1);
                fma2(acc2[i][2], ad, bb2);
                fma2(acc2[i][3], ad, bb3);
            }
        }
        __syncthreads();
    }

    const int cb = col0 + tc*8;   // 8-aligned, never straddles 64/1024 boundaries
    float4 bias0 = *(const float4*)(bias + cb);
    float4 bias1 = *(const float4*)(bias + cb + 4);

    if (MODE == 0) {
        const int which = cb >> 10;          // 0=q 1=k 2=v
        const int rem   = cb & (CC - 1);
        const int h     = rem >> 6;
        const int d0    = rem & (DH - 1);
        float* dstbase = (which == 0) ? g_q : (which == 1) ? g_k : g_v;
        #pragma unroll
        for (int i = 0; i < 8; i++) {
            const int grow = row0 + tr*8 + i;
            const int bb = grow >> 11;           // T = 2048
            const int t  = grow & (TT - 1);
            float* dp = dstbase + ((size_t)(bb*NH + h)*TT + t)*DH + d0;
            float c[8];
            upk2(c[0], c[1], acc2[i][0]);
            upk2(c[2], c[3], acc2[i][1]);
            upk2(c[4], c[5], acc2[i][2]);
            upk2(c[6], c[7], acc2[i][3]);
            float4 r0, r1;
            r0.x = c[0] + bias0.x; r0.y = c[1] + bias0.y;
            r0.z = c[2] + bias0.z; r0.w = c[3] + bias0.w;
            r1.x = c[4] + bias1.x; r1.y = c[5] + bias1.y;
            r1.z = c[6] + bias1.z; r1.w = c[7] + bias1.w;
            *(float4*)(dp + 0) = r0;
            *(float4*)(dp + 4) = r1;
        }
    } else {
        #pragma unroll
        for (int i = 0; i < 8; i++) {
            const int grow = row0 + tr*8 + i;
            float* op = Out + (size_t)grow * N + cb;
            float c[8];
            upk2(c[0], c[1], acc2[i][0]);
            upk2(c[2], c[3], acc2[i][1]);
            upk2(c[4], c[5], acc2[i][2]);
            upk2(c[6], c[7], acc2[i][3]);
            float4 r0, r1;
            r0.x = c[0] + bias0.x; r0.y = c[1] + bias0.y;
            r0.z = c[2] + bias0.z; r0.w = c[3] + bias0.w;
            r1.x = c[4] + bias1.x; r1.y = c[5] + bias1.y;
            r1.z = c[6] + bias1.z; r1.w = c[7] + bias1.w;
            *(float4*)(op + 0) = r0;
            *(float4*)(op + 4) = r1;
        }
    }
}

// ---------------------------------------------------------------------------
// Flash attention, causal, fp32, packed f32x2 matmul loops.
// One CTA = 64 query rows of one (b,h). 256 threads: tr=tid/16 owns rows
// {tr+16i}, tc=tid%16 owns cols {tc+16j}. Softmax reductions: width-16 shfl.
// ---------------------------------------------------------------------------
#define FLASH_SMEM_FLOATS (64*64 + 64*65 + 64*64 + 64*64)
#define FLASH_SMEM_BYTES  (FLASH_SMEM_FLOATS * 4)

__global__ __launch_bounds__(256)
void flash_kernel()
{
    extern __shared__ float sm[];
    float* Qs = sm;              // [64][64]
    float* Ks = Qs + 64*64;      // [64][65]  padded: conflict-free K^T reads
    float* Vs = Ks + 64*65;      // [64][64]
    float* Ps = Vs + 64*64;      // [64][64]

    const int qt = (int)gridDim.x - 1 - (int)blockIdx.x;  // heavy tiles first
    const int bh = blockIdx.y;
    const float* Qg = g_q + (size_t)bh * TT * DH + (size_t)qt * 64 * DH;
    const float* Kg = g_k + (size_t)bh * TT * DH;
    const float* Vg = g_v + (size_t)bh * TT * DH;

    const int tid = threadIdx.x;
    const int tr = tid >> 4;
    const int tc = tid & 15;

    // Load Q tile
    #pragma unroll
    for (int u = 0; u < 4; u++) {
        int idx4 = tid + 256*u;          // 1024 float4s
        int r = idx4 >> 4;
        int c = (idx4 & 15) << 2;
        *(float4*)&Qs[r*64 + c] = *(const float4*)(Qg + r*DH + c);
    }

    float m[4], l[4];
    u64 o2[4][2];    // packed O accumulator: o2[i][p] = O[row i][col pair p]
    #pragma unroll
    for (int i = 0; i < 4; i++) {
        m[i] = -INFINITY; l[i] = 0.f;
        o2[i][0] = 0ull; o2[i][1] = 0ull;
    }

    for (int jc = 0; jc <= qt; jc++) {
        __syncthreads();   // prev iter's smem reads done (also covers Q store)
        #pragma unroll
        for (int u = 0; u < 4; u++) {
            int idx4 = tid + 256*u;
            int r = idx4 >> 4;
            int c = (idx4 & 15) << 2;
            float4 kv = *(const float4*)(Kg + (size_t)(jc*64 + r)*DH + c);
            Ks[r*65 + c + 0] = kv.x;
            Ks[r*65 + c + 1] = kv.y;
            Ks[r*65 + c + 2] = kv.z;
            Ks[r*65 + c + 3] = kv.w;
            *(float4*)&Vs[r*64 + c] = *(const float4*)(Vg + (size_t)(jc*64 + r)*DH + c);
        }
        __syncthreads();

        // S = Q @ K^T, packed over column pairs
        u64 s2[4][2];
        #pragma unroll
        for (int i = 0; i < 4; i++) { s2[i][0] = 0ull; s2[i][1] = 0ull; }

        #pragma unroll 8
        for (int kk = 0; kk < 64; kk++) {
            float qv[4], kv[4];
            #pragma unroll
            for (int i = 0; i < 4; i++) qv[i] = Qs[(tr + 16*i)*64 + kk];
            #pragma unroll
            for (int j = 0; j < 4; j++) kv[j] = Ks[(tc + 16*j)*65 + kk];
            u64 k01 = pk2(kv[0], kv[1]);
            u64 k23 = pk2(kv[2], kv[3]);
            #pragma unroll
            for (int i = 0; i < 4; i++) {
                u64 qd = pk2(qv[i], qv[i]);
                fma2(s2[i][0], qd, k01);
                fma2(s2[i][1], qd, k23);
            }
        }

        // unpack, scale + causal mask (diagonal tile only)
        float s[4][4];
        #pragma unroll
        for (int i = 0; i < 4; i++) {
            upk2(s[i][0], s[i][1], s2[i][0]);
            upk2(s[i][2], s[i][3], s2[i][1]);
        }
        const bool diag = (jc == qt);
        #pragma unroll
        for (int i = 0; i < 4; i++)
            #pragma unroll
            for (int j = 0; j < 4; j++) {
                s[i][j] *= 0.125f;   // 1/sqrt(64)
                if (diag && (tc + 16*j) > (tr + 16*i)) s[i][j] = -INFINITY;
            }

        // online softmax update
        #pragma unroll
        for (int i = 0; i < 4; i++) {
            float v = fmaxf(fmaxf(s[i][0], s[i][1]), fmaxf(s[i][2], s[i][3]));
            #pragma unroll
            for (int off = 8; off >= 1; off >>= 1)
                v = fmaxf(v, __shfl_xor_sync(0xffffffffu, v, off, 16));
            const float mn = fmaxf(m[i], v);      // finite after first tile
            const float alpha = __expf(m[i] - mn);
            float ps = 0.f;
            #pragma unroll
            for (int j = 0; j < 4; j++) {
                const float p = __expf(s[i][j] - mn);
                s[i][j] = p;
                ps += p;
            }
            #pragma unroll
            for (int off = 8; off >= 1; off >>= 1)
                ps += __shfl_xor_sync(0xffffffffu, ps, off, 16);
            l[i] = l[i]*alpha + ps;
            m[i] = mn;
            u64 ad = pk2(alpha, alpha);
            mul2(o2[i][0], ad);
            mul2(o2[i][1], ad);
            #pragma unroll
            for (int j = 0; j < 4; j++)
                Ps[(tr + 16*i)*64 + tc + 16*j] = s[i][j];
        }
        // P rows are produced/consumed within the same half-warp group
        __syncwarp();

        // O += P @ V, packed over column pairs
        #pragma unroll 8
        for (int kk = 0; kk < 64; kk++) {
            float pv[4], vv[4];
            #pragma unroll
            for (int i = 0; i < 4; i++) pv[i] = Ps[(tr + 16*i)*64 + kk];
            #pragma unroll
            for (int j = 0; j < 4; j++) vv[j] = Vs[kk*64 + tc + 16*j];
            u64 v01 = pk2(vv[0], vv[1]);
            u64 v23 = pk2(vv[2], vv[3]);
            #pragma unroll
            for (int i = 0; i < 4; i++) {
                u64 pd = pk2(pv[i], pv[i]);
                fma2(o2[i][0], pd, v01);
                fma2(o2[i][1], pd, v23);
            }
        }
    }

    // normalize + write y in [B,T,C] layout
    const int bb = bh >> 4;
    const int h  = bh & (NH - 1);
    #pragma unroll
    for (int i = 0; i < 4; i++) {
        const float inv = 1.0f / l[i];
        const int row = qt*64 + tr + 16*i;
        float* yp = g_y + ((size_t)bb*TT + row)*CC + h*DH;
        float o[4];
        upk2(o[0], o[1], o2[i][0]);
        upk2(o[2], o[3], o2[i][1]);
        #pragma unroll
        for (int j = 0; j < 4; j++)
            yp[tc + 16*j] = o[j] * inv;
    }
}

// ---------------------------------------------------------------------------
extern "C" void kernel_launch(void* const* d_in, const int* in_sizes, int n_in,
                              void* d_out, int out_size)
{
    (void)in_sizes; (void)n_in; (void)out_size;
    const float* x     = (const float*)d_in[0];
    const float* Wqkv  = (const float*)d_in[1];
    const float* bqkv  = (const float*)d_in[2];
    const float* Wproj = (const float*)d_in[3];
    const float* bproj = (const float*)d_in[4];
    float* out = (float*)d_out;

    // one-time, capture-safe (not a stream op, no allocation)
    static bool attr_set = false;
    if (!attr_set) {
        cudaFuncSetAttribute(flash_kernel,
            cudaFuncAttributeMaxDynamicSharedMemorySize, FLASH_SMEM_BYTES);
        attr_set = true;
    }

    // 1) QKV projection with scatter to [B,H,T,D]
    dim3 gq(3*CC/128, MROWS/128);   // (24, 64)
    sgemm_kernel<0><<<gq, 256>>>(x, Wqkv, bqkv, nullptr, 3*CC, CC);

    // 2) causal flash attention -> g_y [B,T,C]
    dim3 gf(TT/64, NB*NH);          // (32, 64)
    flash_kernel<<<gf, 256, FLASH_SMEM_BYTES>>>();

    // 3) output projection -> d_out
    dim3 gp(CC/128, MROWS/128);     // (8, 64)
    sgemm_kernel<1><<<gp, 256>>>(nullptr, Wproj, bproj, out, CC, CC);
}

// round 7
// speedup vs baseline: 1.5532x; 1.5352x over previous
#include <cuda_runtime.h>
#include <cuda_bf16.h>
#include <math.h>
#include <stdint.h>

#define NB 4
#define NH 16
#define TT 2048
#define DH 64
#define CC 1024
#define MROWS (NB*TT)   // 8192
#define KDIM  1024

// ---------------------------------------------------------------------------
// Scratch (__device__ globals; allocation-free rule)
// ---------------------------------------------------------------------------
__device__ float g_q[NB*NH*TT*DH];   // [B,H,T,D] fp32
__device__ float g_k[NB*NH*TT*DH];
__device__ float g_v[NB*NH*TT*DH];
__device__ float g_y[MROWS*CC];      // [B,T,C] fp32 attention output

// bf16 split planes: [2][rows][K]  (plane 0 = hi, plane 1 = lo)
__device__ __nv_bfloat16 g_xa[2ull*MROWS*KDIM];      // x split
__device__ __nv_bfloat16 g_ya[2ull*MROWS*KDIM];      // y split
__device__ __nv_bfloat16 g_wq[2ull*3072*KDIM];       // Wqkv^T split: [N=3072][K]
__device__ __nv_bfloat16 g_wp[2ull*1024*KDIM];       // Wproj^T split

// ---------------------------------------------------------------------------
// PTX helpers — compute_80-era ops only (harness PTX target lacks the 'a'
// feature set, so tcgen05/TMEM are unavailable; mma.sync+ldmatrix are not).
// ---------------------------------------------------------------------------
__device__ __forceinline__ uint32_t smem_to_u32(const void* p) {
    uint32_t a;
    asm("{ .reg .u64 t; cvta.to.shared.u64 t, %1; cvt.u32.u64 %0, t; }"
        : "=r"(a) : "l"(p));
    return a;
}
__device__ __forceinline__ void cp16(uint32_t saddr, const void* g) {
    asm volatile("cp.async.cg.shared.global [%0], [%1], 16;"
                 :: "r"(saddr), "l"(g) : "memory");
}
__device__ __forceinline__ void ldm_x4(uint32_t (&r)[4], uint32_t addr) {
    asm volatile("ldmatrix.sync.aligned.m8n8.x4.shared.b16 {%0,%1,%2,%3}, [%4];"
        : "=r"(r[0]), "=r"(r[1]), "=r"(r[2]), "=r"(r[3]) : "r"(addr));
}
__device__ __forceinline__ void mma_bf16(float (&d)[4], const uint32_t (&a)[4],
                                         uint32_t b0, uint32_t b1) {
    asm volatile("mma.sync.aligned.m16n8k16.row.col.f32.bf16.bf16.f32 "
        "{%0,%1,%2,%3}, {%4,%5,%6,%7}, {%8,%9}, {%0,%1,%2,%3};"
        : "+f"(d[0]), "+f"(d[1]), "+f"(d[2]), "+f"(d[3])
        : "r"(a[0]), "r"(a[1]), "r"(a[2]), "r"(a[3]), "r"(b0), "r"(b1));
}

// ---------------------------------------------------------------------------
// Conversion kernels: fp32 -> bf16 hi/lo split planes
// ---------------------------------------------------------------------------
__device__ __forceinline__ void bsplit(float x, __nv_bfloat16& h, __nv_bfloat16& l) {
    h = __float2bfloat16(x);
    l = __float2bfloat16(x - __bfloat162float(h));
}

template<int P>   // P=0: x -> g_xa ; P=1: g_y -> g_ya
__global__ __launch_bounds__(256) void conv_act(const float* __restrict__ in)
{
    __nv_bfloat16* out = P ? g_ya : g_xa;
    const float* src = P ? (const float*)g_y : in;
    const size_t i = (size_t)blockIdx.x * 256 + threadIdx.x;   // per float4
    float4 v = ((const float4*)src)[i];
    __nv_bfloat16 h[4], l[4];
    bsplit(v.x, h[0], l[0]); bsplit(v.y, h[1], l[1]);
    bsplit(v.z, h[2], l[2]); bsplit(v.w, h[3], l[3]);
    *(uint2*)(out + 4*i) = *(uint2*)h;
    *(uint2*)(out + (size_t)MROWS*KDIM + 4*i) = *(uint2*)l;
}

template<int N>   // W [K=1024][N] -> out [2][N][1024] (transposed split)
__global__ __launch_bounds__(256) void conv_w_kernel(const float* __restrict__ W)
{
    __nv_bfloat16* out = (N == 3072) ? g_wq : g_wp;
    __shared__ float t[32][33];
    const int k0 = blockIdx.x * 32, n0 = blockIdx.y * 32;
    const int tx = threadIdx.x, ty = threadIdx.y;      // 32 x 8
    #pragma unroll
    for (int i = 0; i < 4; i++)
        t[ty + 8*i][tx] = W[(size_t)(k0 + ty + 8*i) * N + n0 + tx];
    __syncthreads();
    #pragma unroll
    for (int i = 0; i < 4; i++) {
        float v = t[tx][ty + 8*i];
        __nv_bfloat16 h, l; bsplit(v, h, l);
        size_t o = (size_t)(n0 + ty + 8*i) * KDIM + k0 + tx;
        out[o] = h;
        out[(size_t)N * KDIM + o] = l;
    }
}

// ---------------------------------------------------------------------------
// mma.sync split-bf16 GEMM:  C[128x128 tile] = A[M,K] @ B[N,K]^T + bias
// MODE 0: A=g_xa, B=g_wq (N=3072), scatter -> g_q/g_k/g_v
// MODE 1: A=g_ya, B=g_wp (N=1024), -> Out
// 256 threads = 8 warps, warp tile 32(M) x 64(N), BK=32, cp.async dbl-buffer.
// Smem plane: 128 rows x 80B (32 bf16 + 16B pad) -> ldmatrix conflict-free.
// ---------------------------------------------------------------------------
#define PLANE_BYTES 10240          // 128 * 80
#define STAGE_BYTES (4*PLANE_BYTES)
#define GEMM_SMEM_BYTES (2*STAGE_BYTES)   // 81920

template<int MODE>
__global__ __launch_bounds__(256)
void mma_gemm_kernel(const float* __restrict__ bias, float* __restrict__ Out)
{
    extern __shared__ __align__(128) char smem[];
    constexpr int NT = MODE ? 1024 : 3072;
    const __nv_bfloat16* __restrict__ Ab = MODE ? g_ya : g_xa;
    const __nv_bfloat16* __restrict__ Bb = MODE ? g_wp : g_wq;
    constexpr size_t APL = (size_t)MROWS * KDIM;
    constexpr size_t BPL = (size_t)NT * KDIM;

    const int tid  = threadIdx.x;
    const int lane = tid & 31, wid = tid >> 5;
    const int row0 = blockIdx.y * 128, col0 = blockIdx.x * 128;
    const int m0w  = (wid >> 1) * 32;    // warp M offset
    const int n0w  = (wid & 1) * 64;     // warp N offset
    const uint32_t sb = smem_to_u32(smem);

    float acc[2][8][4];
    #pragma unroll
    for (int a = 0; a < 2; a++)
        #pragma unroll
        for (int b = 0; b < 8; b++)
            #pragma unroll
            for (int c = 0; c < 4; c++) acc[a][b][c] = 0.f;

    auto issue = [&](int st, int ck) {
        const int k0 = ck * 32;
        const uint32_t s0 = sb + st * STAGE_BYTES;
        #pragma unroll
        for (int hh = 0; hh < 2; hh++) {
            const int c = tid + hh * 256;       // 512 16B chunks per plane
            const int r = c >> 2, kc = c & 3;
            const uint32_t so = r * 80 + kc * 16;
            const __nv_bfloat16* ga = Ab + (size_t)(row0 + r) * KDIM + k0 + kc * 8;
            cp16(s0 + so,               ga);         // Ah
            cp16(s0 + PLANE_BYTES + so, ga + APL);   // Al
            const __nv_bfloat16* gb = Bb + (size_t)(col0 + r) * KDIM + k0 + kc * 8;
            cp16(s0 + 2*PLANE_BYTES + so, gb);       // Bh
            cp16(s0 + 3*PLANE_BYTES + so, gb + BPL); // Bl
        }
        asm volatile("cp.async.commit_group;" ::: "memory");
    };

    auto compute = [&](int st) {
        const uint32_t s0 = sb + st * STAGE_BYTES;
        const uint32_t rsel = (lane & 15);
        #pragma unroll
        for (int ks = 0; ks < 32; ks += 16) {
            const uint32_t coff = ks * 2 + 16 * (lane >> 4);
            uint32_t ah[2][4], al[2][4];
            #pragma unroll
            for (int mt = 0; mt < 2; mt++) {
                const uint32_t ra = s0 + (m0w + mt*16 + rsel) * 80 + coff;
                ldm_x4(ah[mt], ra);
                ldm_x4(al[mt], ra + PLANE_BYTES);
            }
            #pragma unroll
            for (int nt = 0; nt < 4; nt++) {
                const uint32_t rb = s0 + 2*PLANE_BYTES + (n0w + nt*16 + rsel) * 80 + coff;
                uint32_t bh[4], bl[4];
                ldm_x4(bh, rb);
                ldm_x4(bl, rb + PLANE_BYTES);
                #pragma unroll
                for (int mt = 0; mt < 2; mt++) {
                    // n8 pair: {r0,r2} = (nt*16, klow/khigh), {r1,r3} = (+8)
                    mma_bf16(acc[mt][nt*2],   ah[mt], bh[0], bh[2]);   // hi*hi
                    mma_bf16(acc[mt][nt*2+1], ah[mt], bh[1], bh[3]);
                    mma_bf16(acc[mt][nt*2],   ah[mt], bl[0], bl[2]);   // hi*lo
                    mma_bf16(acc[mt][nt*2+1], ah[mt], bl[1], bl[3]);
                    mma_bf16(acc[mt][nt*2],   al[mt], bh[0], bh[2]);   // lo*hi
                    mma_bf16(acc[mt][nt*2+1], al[mt], bh[1], bh[3]);
                }
            }
        }
    };

    issue(0, 0);
    for (int ck = 0; ck < 32; ck++) {
        if (ck + 1 < 32) {
            issue((ck + 1) & 1, ck + 1);
            asm volatile("cp.async.wait_group 1;" ::: "memory");
        } else {
            asm volatile("cp.async.wait_group 0;" ::: "memory");
        }
        __syncthreads();
        compute(ck & 1);
        __syncthreads();
    }

    // ---- epilogue: c-frags + bias -> global ----
    const int g   = lane >> 2;
    const int cql = (lane & 3) * 2;
    #pragma unroll
    for (int mt = 0; mt < 2; mt++) {
        #pragma unroll
        for (int nt = 0; nt < 8; nt++) {
            const int cg = col0 + n0w + nt * 8 + cql;
            const float b0 = bias[cg], b1 = bias[cg + 1];
            const int r0 = row0 + m0w + mt * 16 + g;
            float2 lo = make_float2(acc[mt][nt][0] + b0, acc[mt][nt][1] + b1);
            float2 hi = make_float2(acc[mt][nt][2] + b0, acc[mt][nt][3] + b1);
            if (MODE == 0) {
                const int which = cg >> 10;
                const int rem = cg & (CC - 1);
                const int h = rem >> 6, d0 = rem & (DH - 1);
                float* base = (which == 0) ? g_q : (which == 1) ? g_k : g_v;
                const int bb0 = r0 >> 11, t0 = r0 & (TT - 1);
                *(float2*)(base + ((size_t)(bb0*NH + h)*TT + t0)*DH + d0) = lo;
                const int r1 = r0 + 8;
                const int bb1 = r1 >> 11, t1 = r1 & (TT - 1);
                *(float2*)(base + ((size_t)(bb1*NH + h)*TT + t1)*DH + d0) = hi;
            } else {
                *(float2*)(Out + (size_t)r0 * CC + cg) = lo;
                *(float2*)(Out + (size_t)(r0 + 8) * CC + cg) = hi;
            }
        }
    }
}

// ---------------------------------------------------------------------------
// Flash attention (unchanged from R4-passing version: fp32 + FFMA2)
// ---------------------------------------------------------------------------
typedef unsigned long long u64;
__device__ __forceinline__ u64 pk2(float lo, float hi) {
    u64 r; asm("mov.b64 %0, {%1, %2};" : "=l"(r) : "f"(lo), "f"(hi)); return r;
}
__device__ __forceinline__ void upk2(float& lo, float& hi, u64 v) {
    asm("mov.b64 {%0, %1}, %2;" : "=f"(lo), "=f"(hi) : "l"(v));
}
__device__ __forceinline__ void fma2(u64& d, u64 a, u64 b) {
    asm("fma.rn.f32x2 %0, %1, %2, %0;" : "+l"(d) : "l"(a), "l"(b));
}
__device__ __forceinline__ void mul2(u64& d, u64 a) {
    asm("mul.rn.f32x2 %0, %0, %1;" : "+l"(d) : "l"(a));
}

#define FLASH_SMEM_FLOATS (64*64 + 64*65 + 64*64 + 64*64)
#define FLASH_SMEM_BYTES  (FLASH_SMEM_FLOATS * 4)

__global__ __launch_bounds__(256)
void flash_kernel()
{
    extern __shared__ float sm[];
    float* Qs = sm;
    float* Ks = Qs + 64*64;      // [64][65]
    float* Vs = Ks + 64*65;
    float* Ps = Vs + 64*64;

    const int qt = (int)gridDim.x - 1 - (int)blockIdx.x;
    const int bh = blockIdx.y;
    const float* Qg = g_q + (size_t)bh * TT * DH + (size_t)qt * 64 * DH;
    const float* Kg = g_k + (size_t)bh * TT * DH;
    const float* Vg = g_v + (size_t)bh * TT * DH;

    const int tid = threadIdx.x;
    const int tr = tid >> 4, tc = tid & 15;

    #pragma unroll
    for (int u = 0; u < 4; u++) {
        int idx4 = tid + 256*u;
        int r = idx4 >> 4, c = (idx4 & 15) << 2;
        *(float4*)&Qs[r*64 + c] = *(const float4*)(Qg + r*DH + c);
    }

    float m[4], l[4];
    u64 o2[4][2];
    #pragma unroll
    for (int i = 0; i < 4; i++) { m[i] = -INFINITY; l[i] = 0.f; o2[i][0] = 0; o2[i][1] = 0; }

    for (int jc = 0; jc <= qt; jc++) {
        __syncthreads();
        #pragma unroll
        for (int u = 0; u < 4; u++) {
            int idx4 = tid + 256*u;
            int r = idx4 >> 4, c = (idx4 & 15) << 2;
            float4 kv = *(const float4*)(Kg + (size_t)(jc*64 + r)*DH + c);
            Ks[r*65 + c + 0] = kv.x; Ks[r*65 + c + 1] = kv.y;
            Ks[r*65 + c + 2] = kv.z; Ks[r*65 + c + 3] = kv.w;
            *(float4*)&Vs[r*64 + c] = *(const float4*)(Vg + (size_t)(jc*64 + r)*DH + c);
        }
        __syncthreads();

        u64 s2[4][2];
        #pragma unroll
        for (int i = 0; i < 4; i++) { s2[i][0] = 0; s2[i][1] = 0; }

        #pragma unroll 8
        for (int kk = 0; kk < 64; kk++) {
            float qv[4], kv[4];
            #pragma unroll
            for (int i = 0; i < 4; i++) qv[i] = Qs[(tr + 16*i)*64 + kk];
            #pragma unroll
            for (int j = 0; j < 4; j++) kv[j] = Ks[(tc + 16*j)*65 + kk];
            u64 k01 = pk2(kv[0], kv[1]), k23 = pk2(kv[2], kv[3]);
            #pragma unroll
            for (int i = 0; i < 4; i++) {
                u64 qd = pk2(qv[i], qv[i]);
                fma2(s2[i][0], qd, k01);
                fma2(s2[i][1], qd, k23);
            }
        }

        float s[4][4];
        #pragma unroll
        for (int i = 0; i < 4; i++) {
            upk2(s[i][0], s[i][1], s2[i][0]);
            upk2(s[i][2], s[i][3], s2[i][1]);
        }
        const bool diag = (jc == qt);
        #pragma unroll
        for (int i = 0; i < 4; i++)
            #pragma unroll
            for (int j = 0; j < 4; j++) {
                s[i][j] *= 0.125f;
                if (diag && (tc + 16*j) > (tr + 16*i)) s[i][j] = -INFINITY;
            }

        #pragma unroll
        for (int i = 0; i < 4; i++) {
            float v = fmaxf(fmaxf(s[i][0], s[i][1]), fmaxf(s[i][2], s[i][3]));
            #pragma unroll
            for (int off = 8; off >= 1; off >>= 1)
                v = fmaxf(v, __shfl_xor_sync(0xffffffffu, v, off, 16));
            const float mn = fmaxf(m[i], v);
            const float alpha = __expf(m[i] - mn);
            float ps = 0.f;
            #pragma unroll
            for (int j = 0; j < 4; j++) {
                const float p = __expf(s[i][j] - mn);
                s[i][j] = p; ps += p;
            }
            #pragma unroll
            for (int off = 8; off >= 1; off >>= 1)
                ps += __shfl_xor_sync(0xffffffffu, ps, off, 16);
            l[i] = l[i]*alpha + ps;
            m[i] = mn;
            u64 ad = pk2(alpha, alpha);
            mul2(o2[i][0], ad); mul2(o2[i][1], ad);
            #pragma unroll
            for (int j = 0; j < 4; j++)
                Ps[(tr + 16*i)*64 + tc + 16*j] = s[i][j];
        }
        __syncwarp();

        #pragma unroll 8
        for (int kk = 0; kk < 64; kk++) {
            float pv[4], vv[4];
            #pragma unroll
            for (int i = 0; i < 4; i++) pv[i] = Ps[(tr + 16*i)*64 + kk];
            #pragma unroll
            for (int j = 0; j < 4; j++) vv[j] = Vs[kk*64 + tc + 16*j];
            u64 v01 = pk2(vv[0], vv[1]), v23 = pk2(vv[2], vv[3]);
            #pragma unroll
            for (int i = 0; i < 4; i++) {
                u64 pd = pk2(pv[i], pv[i]);
                fma2(o2[i][0], pd, v01);
                fma2(o2[i][1], pd, v23);
            }
        }
    }

    const int bb = bh >> 4;
    const int h  = bh & (NH - 1);
    #pragma unroll
    for (int i = 0; i < 4; i++) {
        const float inv = 1.0f / l[i];
        const int row = qt*64 + tr + 16*i;
        float* yp = g_y + ((size_t)bb*TT + row)*CC + h*DH;
        float o[4];
        upk2(o[0], o[1], o2[i][0]);
        upk2(o[2], o[3], o2[i][1]);
        #pragma unroll
        for (int j = 0; j < 4; j++)
            yp[tc + 16*j] = o[j] * inv;
    }
}

// ---------------------------------------------------------------------------
extern "C" void kernel_launch(void* const* d_in, const int* in_sizes, int n_in,
                              void* d_out, int out_size)
{
    (void)in_sizes; (void)n_in; (void)out_size;
    const float* x     = (const float*)d_in[0];
    const float* Wqkv  = (const float*)d_in[1];
    const float* bqkv  = (const float*)d_in[2];
    const float* Wproj = (const float*)d_in[3];
    const float* bproj = (const float*)d_in[4];
    float* out = (float*)d_out;

    static bool attr_set = false;
    if (!attr_set) {
        cudaFuncSetAttribute(flash_kernel,
            cudaFuncAttributeMaxDynamicSharedMemorySize, FLASH_SMEM_BYTES);
        cudaFuncSetAttribute(mma_gemm_kernel<0>,
            cudaFuncAttributeMaxDynamicSharedMemorySize, GEMM_SMEM_BYTES);
        cudaFuncSetAttribute(mma_gemm_kernel<1>,
            cudaFuncAttributeMaxDynamicSharedMemorySize, GEMM_SMEM_BYTES);
        attr_set = true;
    }

    const int act4 = (MROWS * KDIM) / 4;   // float4s per activation tensor

    // 0) splits: x -> g_xa ; Wqkv -> g_wq ; Wproj -> g_wp
    conv_act<0><<<act4 / 256, 256>>>(x);
    conv_w_kernel<3072><<<dim3(KDIM/32, 3072/32), dim3(32, 8)>>>(Wqkv);
    conv_w_kernel<1024><<<dim3(KDIM/32, 1024/32), dim3(32, 8)>>>(Wproj);

    // 1) QKV projection (mma.sync, 3x-bf16) with scatter to [B,H,T,D]
    mma_gemm_kernel<0><<<dim3(3072/128, MROWS/128), 256, GEMM_SMEM_BYTES>>>(bqkv, nullptr);

    // 2) causal flash attention -> g_y [B,T,C]
    dim3 gf(TT/64, NB*NH);
    flash_kernel<<<gf, 256, FLASH_SMEM_BYTES>>>();

    // 3) y split + output projection (mma.sync) -> d_out
    conv_act<1><<<act4 / 256, 256>>>(nullptr);
    mma_gemm_kernel<1><<<dim3(1024/128, MROWS/128), 256, GEMM_SMEM_BYTES>>>(bproj, out);
}

// round 9
// speedup vs baseline: 2.1839x; 1.4061x over previous
#include <cuda_runtime.h>
#include <cuda_bf16.h>
#include <math.h>
#include <stdint.h>

#define NB 4
#define NH 16
#define TT 2048
#define DH 64
#define CC 1024
#define MROWS (NB*TT)   // 8192
#define KDIM  1024

// ---------------------------------------------------------------------------
// Scratch (__device__ globals; allocation-free rule)
// ---------------------------------------------------------------------------
__device__ float g_y[MROWS*CC];      // [B,T,C] fp32 attention output

// split bf16 q/k/v in [B,H,T,D] (hi + lo residual planes)
__device__ __nv_bfloat16 g_qh[NB*NH*TT*DH];
__device__ __nv_bfloat16 g_ql[NB*NH*TT*DH];
__device__ __nv_bfloat16 g_kh[NB*NH*TT*DH];
__device__ __nv_bfloat16 g_kl[NB*NH*TT*DH];
__device__ __nv_bfloat16 g_vh[NB*NH*TT*DH];
__device__ __nv_bfloat16 g_vl[NB*NH*TT*DH];

// bf16 split planes for GEMM inputs: [2][rows][K]
__device__ __nv_bfloat16 g_xa[2ull*MROWS*KDIM];      // x split
__device__ __nv_bfloat16 g_ya[2ull*MROWS*KDIM];      // y split
__device__ __nv_bfloat16 g_wq[2ull*3072*KDIM];       // Wqkv^T split: [N=3072][K]
__device__ __nv_bfloat16 g_wp[2ull*1024*KDIM];       // Wproj^T split

// ---------------------------------------------------------------------------
// PTX helpers — compute_80-era ops only (harness PTX target lacks 'a' features)
// ---------------------------------------------------------------------------
__device__ __forceinline__ uint32_t smem_to_u32(const void* p) {
    uint32_t a;
    asm("{ .reg .u64 t; cvta.to.shared.u64 t, %1; cvt.u32.u64 %0, t; }"
        : "=r"(a) : "l"(p));
    return a;
}
__device__ __forceinline__ void cp16(uint32_t saddr, const void* g) {
    asm volatile("cp.async.cg.shared.global [%0], [%1], 16;"
                 :: "r"(saddr), "l"(g) : "memory");
}
__device__ __forceinline__ void ldm_x4(uint32_t (&r)[4], uint32_t addr) {
    asm volatile("ldmatrix.sync.aligned.m8n8.x4.shared.b16 {%0,%1,%2,%3}, [%4];"
        : "=r"(r[0]), "=r"(r[1]), "=r"(r[2]), "=r"(r[3]) : "r"(addr));
}
__device__ __forceinline__ void ldm_x4_t(uint32_t (&r)[4], uint32_t addr) {
    asm volatile("ldmatrix.sync.aligned.m8n8.x4.trans.shared.b16 {%0,%1,%2,%3}, [%4];"
        : "=r"(r[0]), "=r"(r[1]), "=r"(r[2]), "=r"(r[3]) : "r"(addr));
}
__device__ __forceinline__ void mma_bf16(float (&d)[4], const uint32_t (&a)[4],
                                         uint32_t b0, uint32_t b1) {
    asm volatile("mma.sync.aligned.m16n8k16.row.col.f32.bf16.bf16.f32 "
        "{%0,%1,%2,%3}, {%4,%5,%6,%7}, {%8,%9}, {%0,%1,%2,%3};"
        : "+f"(d[0]), "+f"(d[1]), "+f"(d[2]), "+f"(d[3])
        : "r"(a[0]), "r"(a[1]), "r"(a[2]), "r"(a[3]), "r"(b0), "r"(b1));
}
// pack two fp32 into bf16x2 word: low half = lo_elem
__device__ __forceinline__ uint32_t pack_bf(float lo_elem, float hi_elem) {
    uint32_t r;
    asm("cvt.rn.bf16x2.f32 %0, %1, %2;" : "=r"(r) : "f"(hi_elem), "f"(lo_elem));
    return r;
}

// ---------------------------------------------------------------------------
// Conversion kernels: fp32 -> bf16 hi/lo split planes
// ---------------------------------------------------------------------------
__device__ __forceinline__ void bsplit(float x, __nv_bfloat16& h, __nv_bfloat16& l) {
    h = __float2bfloat16(x);
    l = __float2bfloat16(x - __bfloat162float(h));
}

template<int P>   // P=0: x -> g_xa ; P=1: g_y -> g_ya
__global__ __launch_bounds__(256) void conv_act(const float* __restrict__ in)
{
    __nv_bfloat16* out = P ? g_ya : g_xa;
    const float* src = P ? (const float*)g_y : in;
    const size_t i = (size_t)blockIdx.x * 256 + threadIdx.x;   // per float4
    float4 v = ((const float4*)src)[i];
    __nv_bfloat16 h[4], l[4];
    bsplit(v.x, h[0], l[0]); bsplit(v.y, h[1], l[1]);
    bsplit(v.z, h[2], l[2]); bsplit(v.w, h[3], l[3]);
    *(uint2*)(out + 4*i) = *(uint2*)h;
    *(uint2*)(out + (size_t)MROWS*KDIM + 4*i) = *(uint2*)l;
}

template<int N>   // W [K=1024][N] -> out [2][N][1024] (transposed split)
__global__ __launch_bounds__(256) void conv_w_kernel(const float* __restrict__ W)
{
    __nv_bfloat16* out = (N == 3072) ? g_wq : g_wp;
    __shared__ float t[32][33];
    const int k0 = blockIdx.x * 32, n0 = blockIdx.y * 32;
    const int tx = threadIdx.x, ty = threadIdx.y;      // 32 x 8
    #pragma unroll
    for (int i = 0; i < 4; i++)
        t[ty + 8*i][tx] = W[(size_t)(k0 + ty + 8*i) * N + n0 + tx];
    __syncthreads();
    #pragma unroll
    for (int i = 0; i < 4; i++) {
        float v = t[tx][ty + 8*i];
        __nv_bfloat16 h, l; bsplit(v, h, l);
        size_t o = (size_t)(n0 + ty + 8*i) * KDIM + k0 + tx;
        out[o] = h;
        out[(size_t)N * KDIM + o] = l;
    }
}

// ---------------------------------------------------------------------------
// mma.sync split-bf16 GEMM:  C[128x128 tile] = A[M,K] @ B[N,K]^T + bias
// MODE 0: A=g_xa, B=g_wq (N=3072), epilogue writes SPLIT bf16 q/k/v [B,H,T,D]
// MODE 1: A=g_ya, B=g_wp (N=1024), -> Out fp32
// ---------------------------------------------------------------------------
#define PLANE_BYTES 10240          // 128 * 80
#define STAGE_BYTES (4*PLANE_BYTES)
#define GEMM_SMEM_BYTES (2*STAGE_BYTES)   // 81920

template<int MODE>
__global__ __launch_bounds__(256)
void mma_gemm_kernel(const float* __restrict__ bias, float* __restrict__ Out)
{
    extern __shared__ __align__(128) char smem[];
    constexpr int NT = MODE ? 1024 : 3072;
    const __nv_bfloat16* __restrict__ Ab = MODE ? g_ya : g_xa;
    const __nv_bfloat16* __restrict__ Bb = MODE ? g_wp : g_wq;
    constexpr size_t APL = (size_t)MROWS * KDIM;
    constexpr size_t BPL = (size_t)NT * KDIM;

    const int tid  = threadIdx.x;
    const int lane = tid & 31, wid = tid >> 5;
    const int row0 = blockIdx.y * 128, col0 = blockIdx.x * 128;
    const int m0w  = (wid >> 1) * 32;    // warp M offset
    const int n0w  = (wid & 1) * 64;     // warp N offset
    const uint32_t sb = smem_to_u32(smem);

    float acc[2][8][4];
    #pragma unroll
    for (int a = 0; a < 2; a++)
        #pragma unroll
        for (int b = 0; b < 8; b++)
            #pragma unroll
            for (int c = 0; c < 4; c++) acc[a][b][c] = 0.f;

    auto issue = [&](int st, int ck) {
        const int k0 = ck * 32;
        const uint32_t s0 = sb + st * STAGE_BYTES;
        #pragma unroll
        for (int hh = 0; hh < 2; hh++) {
            const int c = tid + hh * 256;       // 512 16B chunks per plane
            const int r = c >> 2, kc = c & 3;
            const uint32_t so = r * 80 + kc * 16;
            const __nv_bfloat16* ga = Ab + (size_t)(row0 + r) * KDIM + k0 + kc * 8;
            cp16(s0 + so,               ga);         // Ah
            cp16(s0 + PLANE_BYTES + so, ga + APL);   // Al
            const __nv_bfloat16* gb = Bb + (size_t)(col0 + r) * KDIM + k0 + kc * 8;
            cp16(s0 + 2*PLANE_BYTES + so, gb);       // Bh
            cp16(s0 + 3*PLANE_BYTES + so, gb + BPL); // Bl
        }
        asm volatile("cp.async.commit_group;" ::: "memory");
    };

    auto compute = [&](int st) {
        const uint32_t s0 = sb + st * STAGE_BYTES;
        const uint32_t rsel = (lane & 15);
        #pragma unroll
        for (int ks = 0; ks < 32; ks += 16) {
            const uint32_t coff = ks * 2 + 16 * (lane >> 4);
            uint32_t ah[2][4], al[2][4];
            #pragma unroll
            for (int mt = 0; mt < 2; mt++) {
                const uint32_t ra = s0 + (m0w + mt*16 + rsel) * 80 + coff;
                ldm_x4(ah[mt], ra);
                ldm_x4(al[mt], ra + PLANE_BYTES);
            }
            #pragma unroll
            for (int nt = 0; nt < 4; nt++) {
                const uint32_t rb = s0 + 2*PLANE_BYTES + (n0w + nt*16 + rsel) * 80 + coff;
                uint32_t bh[4], bl[4];
                ldm_x4(bh, rb);
                ldm_x4(bl, rb + PLANE_BYTES);
                #pragma unroll
                for (int mt = 0; mt < 2; mt++) {
                    mma_bf16(acc[mt][nt*2],   ah[mt], bh[0], bh[2]);   // hi*hi
                    mma_bf16(acc[mt][nt*2+1], ah[mt], bh[1], bh[3]);
                    mma_bf16(acc[mt][nt*2],   ah[mt], bl[0], bl[2]);   // hi*lo
                    mma_bf16(acc[mt][nt*2+1], ah[mt], bl[1], bl[3]);
                    mma_bf16(acc[mt][nt*2],   al[mt], bh[0], bh[2]);   // lo*hi
                    mma_bf16(acc[mt][nt*2+1], al[mt], bh[1], bh[3]);
                }
            }
        }
    };

    issue(0, 0);
    for (int ck = 0; ck < 32; ck++) {
        if (ck + 1 < 32) {
            issue((ck + 1) & 1, ck + 1);
            asm volatile("cp.async.wait_group 1;" ::: "memory");
        } else {
            asm volatile("cp.async.wait_group 0;" ::: "memory");
        }
        __syncthreads();
        compute(ck & 1);
        __syncthreads();
    }

    // ---- epilogue ----
    const int g   = lane >> 2;
    const int cql = (lane & 3) * 2;
    #pragma unroll
    for (int mt = 0; mt < 2; mt++) {
        #pragma unroll
        for (int nt = 0; nt < 8; nt++) {
            const int cg = col0 + n0w + nt * 8 + cql;
            const float b0 = bias[cg], b1 = bias[cg + 1];
            const int r0 = row0 + m0w + mt * 16 + g;
            const int r1 = r0 + 8;
            float2 lo = make_float2(acc[mt][nt][0] + b0, acc[mt][nt][1] + b1);
            float2 hi = make_float2(acc[mt][nt][2] + b0, acc[mt][nt][3] + b1);
            if (MODE == 0) {
                const int which = cg >> 10;
                const int rem = cg & (CC - 1);
                const int h = rem >> 6, d0 = rem & (DH - 1);
                __nv_bfloat16 *ph, *pl;
                if (which == 0)      { ph = g_qh; pl = g_ql; }
                else if (which == 1) { ph = g_kh; pl = g_kl; }
                else                 { ph = g_vh; pl = g_vl; }
                {
                    uint32_t hw = pack_bf(lo.x, lo.y);
                    float f0 = __uint_as_float(hw << 16);
                    float f1 = __uint_as_float(hw & 0xFFFF0000u);
                    uint32_t lw = pack_bf(lo.x - f0, lo.y - f1);
                    const int bb = r0 >> 11, t = r0 & (TT - 1);
                    size_t off = ((size_t)(bb*NH + h)*TT + t)*DH + d0;
                    *(uint32_t*)(ph + off) = hw;
                    *(uint32_t*)(pl + off) = lw;
                }
                {
                    uint32_t hw = pack_bf(hi.x, hi.y);
                    float f0 = __uint_as_float(hw << 16);
                    float f1 = __uint_as_float(hw & 0xFFFF0000u);
                    uint32_t lw = pack_bf(hi.x - f0, hi.y - f1);
                    const int bb = r1 >> 11, t = r1 & (TT - 1);
                    size_t off = ((size_t)(bb*NH + h)*TT + t)*DH + d0;
                    *(uint32_t*)(ph + off) = hw;
                    *(uint32_t*)(pl + off) = lw;
                }
            } else {
                *(float2*)(Out + (size_t)r0 * CC + cg) = lo;
                *(float2*)(Out + (size_t)r1 * CC + cg) = hi;
            }
        }
    }
}

// ---------------------------------------------------------------------------
// Flash attention on mma.sync, 3-term bf16 split everywhere.
// CTA = 64 q-rows of one (b,h), 4 warps (m16 each), Bc=64 per iteration.
// Smem planes: 64 rows x 144B (64 bf16 + 16B pad), conflict-free ldmatrix.
// ---------------------------------------------------------------------------
#define QPL 9216                     // 64 * 144
#define FL_STAGE (4*QPL)             // Kh,Kl,Vh,Vl
#define FL_SMEM_BYTES (2*QPL + 2*FL_STAGE)   // 92160

__global__ __launch_bounds__(128)
void flash_mma_kernel()
{
    extern __shared__ __align__(128) char smem[];
    const uint32_t sb = smem_to_u32(smem);
    const int tid = threadIdx.x, lane = tid & 31, wid = tid >> 5;
    const int qt = (int)gridDim.x - 1 - (int)blockIdx.x;   // heavy tiles first
    const int bh = blockIdx.y;
    const size_t base = (size_t)bh * TT * DH;

    // Q planes -> smem (part of cp.async group 0)
    {
        const __nv_bfloat16* q0 = g_qh + base + (size_t)qt * 64 * DH;
        const __nv_bfloat16* q1 = g_ql + base + (size_t)qt * 64 * DH;
        #pragma unroll
        for (int i = 0; i < 4; i++) {
            const int ch = tid + i * 128;        // 0..511
            const int r = ch >> 3, c = ch & 7;
            cp16(sb +       r*144 + c*16, q0 + r*DH + c*8);
            cp16(sb + QPL + r*144 + c*16, q1 + r*DH + c*8);
        }
    }
    const __nv_bfloat16* kh = g_kh + base;
    const __nv_bfloat16* kl = g_kl + base;
    const __nv_bfloat16* vh = g_vh + base;
    const __nv_bfloat16* vl = g_vl + base;

    auto issue_kv = [&](int jc, int st) {
        const uint32_t d0 = sb + 2*QPL + st*FL_STAGE;
        const size_t g0 = (size_t)jc * 64 * DH;
        #pragma unroll
        for (int i = 0; i < 4; i++) {
            const int ch = tid + i * 128;
            const int r = ch >> 3, c = ch & 7;
            const uint32_t so = r*144 + c*16;
            const size_t go = g0 + (size_t)r*DH + c*8;
            cp16(d0 +         so, kh + go);
            cp16(d0 +   QPL + so, kl + go);
            cp16(d0 + 2*QPL + so, vh + go);
            cp16(d0 + 3*QPL + so, vl + go);
        }
        asm volatile("cp.async.commit_group;" ::: "memory");
    };

    issue_kv(0, 0);   // group 0 (includes Q)

    uint32_t qfh[4][4], qfl[4][4];
    float oacc[8][4];
    #pragma unroll
    for (int nt = 0; nt < 8; nt++)
        #pragma unroll
        for (int e = 0; e < 4; e++) oacc[nt][e] = 0.f;
    float m0 = -INFINITY, m1 = -INFINITY, l0 = 0.f, l1 = 0.f;

    const int rsel = lane & 15;
    const uint32_t chalf = 16 * (lane >> 4);
    const int vrow = (lane & 7) + 8 * ((lane >> 4) & 1);
    const uint32_t vcol = 16 * ((lane >> 3) & 1);

    for (int jc = 0; jc <= qt; jc++) {
        if (jc < qt) {
            issue_kv(jc + 1, (jc + 1) & 1);
            asm volatile("cp.async.wait_group 1;" ::: "memory");
        } else {
            asm volatile("cp.async.wait_group 0;" ::: "memory");
        }
        __syncthreads();

        if (jc == 0) {   // Q fragments once
            #pragma unroll
            for (int ku = 0; ku < 4; ku++) {
                const uint32_t qa = sb + (uint32_t)((wid << 4) + rsel)*144 + ku*32 + chalf;
                ldm_x4(qfh[ku], qa);
                ldm_x4(qfl[ku], qa + QPL);
            }
        }

        const uint32_t s0 = sb + 2*QPL + (jc & 1)*FL_STAGE;

        // ---- S = Q @ K^T (3-term split) ----
        float s[8][4];
        #pragma unroll
        for (int nt = 0; nt < 8; nt++)
            #pragma unroll
            for (int e = 0; e < 4; e++) s[nt][e] = 0.f;

        #pragma unroll
        for (int ku = 0; ku < 4; ku++) {
            #pragma unroll
            for (int ng = 0; ng < 4; ng++) {
                uint32_t kh4[4], kl4[4];
                const uint32_t ka = s0 + (uint32_t)(ng*16 + rsel)*144 + ku*32 + chalf;
                ldm_x4(kh4, ka);
                ldm_x4(kl4, ka + QPL);
                mma_bf16(s[ng*2],   qfh[ku], kh4[0], kh4[2]);
                mma_bf16(s[ng*2+1], qfh[ku], kh4[1], kh4[3]);
                mma_bf16(s[ng*2],   qfh[ku], kl4[0], kl4[2]);
                mma_bf16(s[ng*2+1], qfh[ku], kl4[1], kl4[3]);
                mma_bf16(s[ng*2],   qfl[ku], kh4[0], kh4[2]);
                mma_bf16(s[ng*2+1], qfl[ku], kh4[1], kh4[3]);
            }
        }

        // ---- scale + causal mask ----
        #pragma unroll
        for (int nt = 0; nt < 8; nt++)
            #pragma unroll
            for (int e = 0; e < 4; e++) s[nt][e] *= 0.125f;
        if (jc == qt) {
            const int r0l = (wid << 4) + (lane >> 2);
            const int cb  = (lane & 3) * 2;
            #pragma unroll
            for (int nt = 0; nt < 8; nt++) {
                const int c0 = nt*8 + cb;
                if (c0     > r0l    ) s[nt][0] = -INFINITY;
                if (c0 + 1 > r0l    ) s[nt][1] = -INFINITY;
                if (c0     > r0l + 8) s[nt][2] = -INFINITY;
                if (c0 + 1 > r0l + 8) s[nt][3] = -INFINITY;
            }
        }

        // ---- online softmax (rows g and g+8; row on 4 lanes) ----
        float mx0 = -INFINITY, mx1 = -INFINITY;
        #pragma unroll
        for (int nt = 0; nt < 8; nt++) {
            mx0 = fmaxf(mx0, fmaxf(s[nt][0], s[nt][1]));
            mx1 = fmaxf(mx1, fmaxf(s[nt][2], s[nt][3]));
        }
        mx0 = fmaxf(mx0, __shfl_xor_sync(0xffffffffu, mx0, 1));
        mx0 = fmaxf(mx0, __shfl_xor_sync(0xffffffffu, mx0, 2));
        mx1 = fmaxf(mx1, __shfl_xor_sync(0xffffffffu, mx1, 1));
        mx1 = fmaxf(mx1, __shfl_xor_sync(0xffffffffu, mx1, 2));
        const float mn0 = fmaxf(m0, mx0), mn1 = fmaxf(m1, mx1);
        const float a0 = __expf(m0 - mn0), a1 = __expf(m1 - mn1);
        float sum0 = 0.f, sum1 = 0.f;
        #pragma unroll
        for (int nt = 0; nt < 8; nt++) {
            s[nt][0] = __expf(s[nt][0] - mn0); sum0 += s[nt][0];
            s[nt][1] = __expf(s[nt][1] - mn0); sum0 += s[nt][1];
            s[nt][2] = __expf(s[nt][2] - mn1); sum1 += s[nt][2];
            s[nt][3] = __expf(s[nt][3] - mn1); sum1 += s[nt][3];
        }
        sum0 += __shfl_xor_sync(0xffffffffu, sum0, 1);
        sum0 += __shfl_xor_sync(0xffffffffu, sum0, 2);
        sum1 += __shfl_xor_sync(0xffffffffu, sum1, 1);
        sum1 += __shfl_xor_sync(0xffffffffu, sum1, 2);
        l0 = l0 * a0 + sum0;  m0 = mn0;
        l1 = l1 * a1 + sum1;  m1 = mn1;
        #pragma unroll
        for (int nt = 0; nt < 8; nt++) {
            oacc[nt][0] *= a0; oacc[nt][1] *= a0;
            oacc[nt][2] *= a1; oacc[nt][3] *= a1;
        }

        // ---- O += P @ V (P reinterpreted from S c-frags, 3-term split) ----
        #pragma unroll
        for (int u = 0; u < 4; u++) {
            uint32_t pah[4], pal[4];
            #pragma unroll
            for (int t = 0; t < 4; t++) {
                const int j = 2*u + (t >> 1);
                const int e0 = (t & 1) * 2;
                pah[t] = pack_bf(s[j][e0], s[j][e0 + 1]);
                const float f0 = __uint_as_float(pah[t] << 16);
                const float f1 = __uint_as_float(pah[t] & 0xFFFF0000u);
                pal[t] = pack_bf(s[j][e0] - f0, s[j][e0 + 1] - f1);
            }
            #pragma unroll
            for (int dg = 0; dg < 4; dg++) {
                uint32_t vh4[4], vl4[4];
                const uint32_t va = s0 + 2*QPL + (uint32_t)(u*16 + vrow)*144 + dg*32 + vcol;
                ldm_x4_t(vh4, va);
                ldm_x4_t(vl4, va + QPL);
                mma_bf16(oacc[dg*2],   pah, vh4[0], vh4[2]);
                mma_bf16(oacc[dg*2+1], pah, vh4[1], vh4[3]);
                mma_bf16(oacc[dg*2],   pah, vl4[0], vl4[2]);
                mma_bf16(oacc[dg*2+1], pah, vl4[1], vl4[3]);
                mma_bf16(oacc[dg*2],   pal, vh4[0], vh4[2]);
                mma_bf16(oacc[dg*2+1], pal, vh4[1], vh4[3]);
            }
        }
        __syncthreads();   // stage reads done before refill
    }

    // ---- normalize + write y [B,T,C] fp32 ----
    const int g  = lane >> 2;
    const int t2 = (lane & 3) * 2;
    const int bb = bh >> 4, hh = bh & (NH - 1);
    const int row0 = qt*64 + (wid << 4) + g;
    const float inv0 = 1.0f / l0, inv1 = 1.0f / l1;
    float* y0 = g_y + ((size_t)bb*TT + row0)*CC + hh*DH;
    float* y1 = g_y + ((size_t)bb*TT + row0 + 8)*CC + hh*DH;
    #pragma unroll
    for (int nt = 0; nt < 8; nt++) {
        *(float2*)(y0 + nt*8 + t2) = make_float2(oacc[nt][0]*inv0, oacc[nt][1]*inv0);
        *(float2*)(y1 + nt*8 + t2) = make_float2(oacc[nt][2]*inv1, oacc[nt][3]*inv1);
    }
}

// ---------------------------------------------------------------------------
extern "C" void kernel_launch(void* const* d_in, const int* in_sizes, int n_in,
                              void* d_out, int out_size)
{
    (void)in_sizes; (void)n_in; (void)out_size;
    const float* x     = (const float*)d_in[0];
    const float* Wqkv  = (const float*)d_in[1];
    const float* bqkv  = (const float*)d_in[2];
    const float* Wproj = (const float*)d_in[3];
    const float* bproj = (const float*)d_in[4];
    float* out = (float*)d_out;

    static bool attr_set = false;
    if (!attr_set) {
        cudaFuncSetAttribute(flash_mma_kernel,
            cudaFuncAttributeMaxDynamicSharedMemorySize, FL_SMEM_BYTES);
        cudaFuncSetAttribute(mma_gemm_kernel<0>,
            cudaFuncAttributeMaxDynamicSharedMemorySize, GEMM_SMEM_BYTES);
        cudaFuncSetAttribute(mma_gemm_kernel<1>,
            cudaFuncAttributeMaxDynamicSharedMemorySize, GEMM_SMEM_BYTES);
        attr_set = true;
    }

    const int act4 = (MROWS * KDIM) / 4;

    // 0) splits: x -> g_xa ; Wqkv -> g_wq ; Wproj -> g_wp
    conv_act<0><<<act4 / 256, 256>>>(x);
    conv_w_kernel<3072><<<dim3(KDIM/32, 3072/32), dim3(32, 8)>>>(Wqkv);
    conv_w_kernel<1024><<<dim3(KDIM/32, 1024/32), dim3(32, 8)>>>(Wproj);

    // 1) QKV projection -> split bf16 q/k/v [B,H,T,D]
    mma_gemm_kernel<0><<<dim3(3072/128, MROWS/128), 256, GEMM_SMEM_BYTES>>>(bqkv, nullptr);

    // 2) causal flash attention (tensor cores) -> g_y [B,T,C]
    flash_mma_kernel<<<dim3(TT/64, NB*NH), 128, FL_SMEM_BYTES>>>();

    // 3) y split + output projection -> d_out
    conv_act<1><<<act4 / 256, 256>>>(nullptr);
    mma_gemm_kernel<1><<<dim3(1024/128, MROWS/128), 256, GEMM_SMEM_BYTES>>>(bproj, out);
}

// round 10
// speedup vs baseline: 2.5069x; 1.1479x over previous
#include <cuda_runtime.h>
#include <cuda_bf16.h>
#include <cuda_fp16.h>
#include <math.h>
#include <stdint.h>

#define NB 4
#define NH 16
#define TT 2048
#define DH 64
#define CC 1024
#define MROWS (NB*TT)   // 8192
#define KDIM  1024

// ---------------------------------------------------------------------------
// Scratch (__device__ globals; allocation-free rule)
// ---------------------------------------------------------------------------
__device__ float g_y[MROWS*CC];      // [B,T,C] fp32 attention output

// split q/k in bf16, v in fp16 (PV runs fp16), all [B,H,T,D] hi+lo planes
__device__ __nv_bfloat16 g_qh[NB*NH*TT*DH];
__device__ __nv_bfloat16 g_ql[NB*NH*TT*DH];
__device__ __nv_bfloat16 g_kh[NB*NH*TT*DH];
__device__ __nv_bfloat16 g_kl[NB*NH*TT*DH];
__device__ __half        g_vh[NB*NH*TT*DH];
__device__ __half        g_vl[NB*NH*TT*DH];

// bf16 split planes for GEMM inputs: [2][rows][K]
__device__ __nv_bfloat16 g_xa[2ull*MROWS*KDIM];      // x split
__device__ __nv_bfloat16 g_ya[2ull*MROWS*KDIM];      // y split
__device__ __nv_bfloat16 g_wq[2ull*3072*KDIM];       // Wqkv^T split: [N=3072][K]
__device__ __nv_bfloat16 g_wp[2ull*1024*KDIM];       // Wproj^T split

// ---------------------------------------------------------------------------
// PTX helpers — compute_80-era ops only (harness PTX target lacks 'a' features)
// ---------------------------------------------------------------------------
__device__ __forceinline__ uint32_t smem_to_u32(const void* p) {
    uint32_t a;
    asm("{ .reg .u64 t; cvta.to.shared.u64 t, %1; cvt.u32.u64 %0, t; }"
        : "=r"(a) : "l"(p));
    return a;
}
__device__ __forceinline__ void cp16(uint32_t saddr, const void* g) {
    asm volatile("cp.async.cg.shared.global [%0], [%1], 16;"
                 :: "r"(saddr), "l"(g) : "memory");
}
__device__ __forceinline__ void ldm_x4(uint32_t (&r)[4], uint32_t addr) {
    asm volatile("ldmatrix.sync.aligned.m8n8.x4.shared.b16 {%0,%1,%2,%3}, [%4];"
        : "=r"(r[0]), "=r"(r[1]), "=r"(r[2]), "=r"(r[3]) : "r"(addr));
}
__device__ __forceinline__ void ldm_x4_t(uint32_t (&r)[4], uint32_t addr) {
    asm volatile("ldmatrix.sync.aligned.m8n8.x4.trans.shared.b16 {%0,%1,%2,%3}, [%4];"
        : "=r"(r[0]), "=r"(r[1]), "=r"(r[2]), "=r"(r[3]) : "r"(addr));
}
__device__ __forceinline__ void mma_bf16(float (&d)[4], const uint32_t (&a)[4],
                                         uint32_t b0, uint32_t b1) {
    asm volatile("mma.sync.aligned.m16n8k16.row.col.f32.bf16.bf16.f32 "
        "{%0,%1,%2,%3}, {%4,%5,%6,%7}, {%8,%9}, {%0,%1,%2,%3};"
        : "+f"(d[0]), "+f"(d[1]), "+f"(d[2]), "+f"(d[3])
        : "r"(a[0]), "r"(a[1]), "r"(a[2]), "r"(a[3]), "r"(b0), "r"(b1));
}
__device__ __forceinline__ void mma_f16(float (&d)[4], const uint32_t (&a)[4],
                                        uint32_t b0, uint32_t b1) {
    asm volatile("mma.sync.aligned.m16n8k16.row.col.f32.f16.f16.f32 "
        "{%0,%1,%2,%3}, {%4,%5,%6,%7}, {%8,%9}, {%0,%1,%2,%3};"
        : "+f"(d[0]), "+f"(d[1]), "+f"(d[2]), "+f"(d[3])
        : "r"(a[0]), "r"(a[1]), "r"(a[2]), "r"(a[3]), "r"(b0), "r"(b1));
}
// pack two fp32 into bf16x2 word: low half = lo_elem
__device__ __forceinline__ uint32_t pack_bf(float lo_elem, float hi_elem) {
    uint32_t r;
    asm("cvt.rn.bf16x2.f32 %0, %1, %2;" : "=r"(r) : "f"(hi_elem), "f"(lo_elem));
    return r;
}
// pack two fp32 into f16x2 word: low half = lo_elem
__device__ __forceinline__ uint32_t pack_hf(float lo_elem, float hi_elem) {
    __half2 h = __floats2half2_rn(lo_elem, hi_elem);
    return *(uint32_t*)&h;
}

// ---------------------------------------------------------------------------
// Conversion kernels: fp32 -> bf16 hi/lo split planes
// ---------------------------------------------------------------------------
__device__ __forceinline__ void bsplit(float x, __nv_bfloat16& h, __nv_bfloat16& l) {
    h = __float2bfloat16(x);
    l = __float2bfloat16(x - __bfloat162float(h));
}

template<int P>   // P=0: x -> g_xa ; P=1: g_y -> g_ya
__global__ __launch_bounds__(256) void conv_act(const float* __restrict__ in)
{
    __nv_bfloat16* out = P ? g_ya : g_xa;
    const float* src = P ? (const float*)g_y : in;
    const size_t i = (size_t)blockIdx.x * 256 + threadIdx.x;   // per float4
    float4 v = ((const float4*)src)[i];
    __nv_bfloat16 h[4], l[4];
    bsplit(v.x, h[0], l[0]); bsplit(v.y, h[1], l[1]);
    bsplit(v.z, h[2], l[2]); bsplit(v.w, h[3], l[3]);
    *(uint2*)(out + 4*i) = *(uint2*)h;
    *(uint2*)(out + (size_t)MROWS*KDIM + 4*i) = *(uint2*)l;
}

template<int N>   // W [K=1024][N] -> out [2][N][1024] (transposed split)
__global__ __launch_bounds__(256) void conv_w_kernel(const float* __restrict__ W)
{
    __nv_bfloat16* out = (N == 3072) ? g_wq : g_wp;
    __shared__ float t[32][33];
    const int k0 = blockIdx.x * 32, n0 = blockIdx.y * 32;
    const int tx = threadIdx.x, ty = threadIdx.y;      // 32 x 8
    #pragma unroll
    for (int i = 0; i < 4; i++)
        t[ty + 8*i][tx] = W[(size_t)(k0 + ty + 8*i) * N + n0 + tx];
    __syncthreads();
    #pragma unroll
    for (int i = 0; i < 4; i++) {
        float v = t[tx][ty + 8*i];
        __nv_bfloat16 h, l; bsplit(v, h, l);
        size_t o = (size_t)(n0 + ty + 8*i) * KDIM + k0 + tx;
        out[o] = h;
        out[(size_t)N * KDIM + o] = l;
    }
}

// ---------------------------------------------------------------------------
// mma.sync split-bf16 GEMM:  C[128x128 tile] = A[M,K] @ B[N,K]^T + bias
// MODE 0: A=g_xa, B=g_wq (N=3072), epilogue writes split q/k (bf16), v (fp16)
// MODE 1: A=g_ya, B=g_wp (N=1024), -> Out fp32
// __launch_bounds__(256,2): regs<=128 so 2 CTAs/SM (R8 regressed to 130/1CTA)
// ---------------------------------------------------------------------------
#define PLANE_BYTES 10240          // 128 * 80
#define STAGE_BYTES (4*PLANE_BYTES)
#define GEMM_SMEM_BYTES (2*STAGE_BYTES)   // 81920

template<int MODE>
__global__ __launch_bounds__(256, 2)
void mma_gemm_kernel(const float* __restrict__ bias, float* __restrict__ Out)
{
    extern __shared__ __align__(128) char smem[];
    constexpr int NT = MODE ? 1024 : 3072;
    const __nv_bfloat16* __restrict__ Ab = MODE ? g_ya : g_xa;
    const __nv_bfloat16* __restrict__ Bb = MODE ? g_wp : g_wq;
    constexpr size_t APL = (size_t)MROWS * KDIM;
    constexpr size_t BPL = (size_t)NT * KDIM;

    const int tid  = threadIdx.x;
    const int lane = tid & 31, wid = tid >> 5;
    const int row0 = blockIdx.y * 128, col0 = blockIdx.x * 128;
    const int m0w  = (wid >> 1) * 32;    // warp M offset
    const int n0w  = (wid & 1) * 64;     // warp N offset
    const uint32_t sb = smem_to_u32(smem);

    float acc[2][8][4];
    #pragma unroll
    for (int a = 0; a < 2; a++)
        #pragma unroll
        for (int b = 0; b < 8; b++)
            #pragma unroll
            for (int c = 0; c < 4; c++) acc[a][b][c] = 0.f;

    auto issue = [&](int st, int ck) {
        const int k0 = ck * 32;
        const uint32_t s0 = sb + st * STAGE_BYTES;
        #pragma unroll
        for (int hh = 0; hh < 2; hh++) {
            const int c = tid + hh * 256;       // 512 16B chunks per plane
            const int r = c >> 2, kc = c & 3;
            const uint32_t so = r * 80 + kc * 16;
            const __nv_bfloat16* ga = Ab + (size_t)(row0 + r) * KDIM + k0 + kc * 8;
            cp16(s0 + so,               ga);         // Ah
            cp16(s0 + PLANE_BYTES + so, ga + APL);   // Al
            const __nv_bfloat16* gb = Bb + (size_t)(col0 + r) * KDIM + k0 + kc * 8;
            cp16(s0 + 2*PLANE_BYTES + so, gb);       // Bh
            cp16(s0 + 3*PLANE_BYTES + so, gb + BPL); // Bl
        }
        asm volatile("cp.async.commit_group;" ::: "memory");
    };

    auto compute = [&](int st) {
        const uint32_t s0 = sb + st * STAGE_BYTES;
        const uint32_t rsel = (lane & 15);
        #pragma unroll
        for (int ks = 0; ks < 32; ks += 16) {
            const uint32_t coff = ks * 2 + 16 * (lane >> 4);
            uint32_t ah[2][4], al[2][4];
            #pragma unroll
            for (int mt = 0; mt < 2; mt++) {
                const uint32_t ra = s0 + (m0w + mt*16 + rsel) * 80 + coff;
                ldm_x4(ah[mt], ra);
                ldm_x4(al[mt], ra + PLANE_BYTES);
            }
            #pragma unroll
            for (int nt = 0; nt < 4; nt++) {
                const uint32_t rb = s0 + 2*PLANE_BYTES + (n0w + nt*16 + rsel) * 80 + coff;
                uint32_t bh[4], bl[4];
                ldm_x4(bh, rb);
                ldm_x4(bl, rb + PLANE_BYTES);
                #pragma unroll
                for (int mt = 0; mt < 2; mt++) {
                    mma_bf16(acc[mt][nt*2],   ah[mt], bh[0], bh[2]);   // hi*hi
                    mma_bf16(acc[mt][nt*2+1], ah[mt], bh[1], bh[3]);
                    mma_bf16(acc[mt][nt*2],   ah[mt], bl[0], bl[2]);   // hi*lo
                    mma_bf16(acc[mt][nt*2+1], ah[mt], bl[1], bl[3]);
                    mma_bf16(acc[mt][nt*2],   al[mt], bh[0], bh[2]);   // lo*hi
                    mma_bf16(acc[mt][nt*2+1], al[mt], bh[1], bh[3]);
                }
            }
        }
    };

    issue(0, 0);
    for (int ck = 0; ck < 32; ck++) {
        if (ck + 1 < 32) {
            issue((ck + 1) & 1, ck + 1);
            asm volatile("cp.async.wait_group 1;" ::: "memory");
        } else {
            asm volatile("cp.async.wait_group 0;" ::: "memory");
        }
        __syncthreads();
        compute(ck & 1);
        __syncthreads();
    }

    // ---- epilogue ----
    const int g   = lane >> 2;
    const int cql = (lane & 3) * 2;
    #pragma unroll
    for (int mt = 0; mt < 2; mt++) {
        #pragma unroll
        for (int nt = 0; nt < 8; nt++) {
            const int cg = col0 + n0w + nt * 8 + cql;
            const float b0 = bias[cg], b1 = bias[cg + 1];
            const int r0 = row0 + m0w + mt * 16 + g;
            const int r1 = r0 + 8;
            float2 lo = make_float2(acc[mt][nt][0] + b0, acc[mt][nt][1] + b1);
            float2 hi = make_float2(acc[mt][nt][2] + b0, acc[mt][nt][3] + b1);
            if (MODE == 0) {
                const int which = cg >> 10;
                const int rem = cg & (CC - 1);
                const int h = rem >> 6, d0 = rem & (DH - 1);
                uint32_t *ph, *pl;
                if (which == 0)      { ph = (uint32_t*)g_qh; pl = (uint32_t*)g_ql; }
                else if (which == 1) { ph = (uint32_t*)g_kh; pl = (uint32_t*)g_kl; }
                else                 { ph = (uint32_t*)g_vh; pl = (uint32_t*)g_vl; }
                #pragma unroll
                for (int half2i = 0; half2i < 2; half2i++) {
                    const float2 v2 = half2i ? hi : lo;
                    const int rr = half2i ? r1 : r0;
                    uint32_t hw, lw;
                    if (which == 2) {    // fp16 split for V
                        hw = pack_hf(v2.x, v2.y);
                        __half2 hh = *(__half2*)&hw;
                        lw = pack_hf(v2.x - __half2float(hh.x),
                                     v2.y - __half2float(hh.y));
                    } else {             // bf16 split for Q,K
                        hw = pack_bf(v2.x, v2.y);
                        float f0 = __uint_as_float(hw << 16);
                        float f1 = __uint_as_float(hw & 0xFFFF0000u);
                        lw = pack_bf(v2.x - f0, v2.y - f1);
                    }
                    const int bb = rr >> 11, t = rr & (TT - 1);
                    size_t off = (((size_t)(bb*NH + h)*TT + t)*DH + d0) >> 1;
                    ph[off] = hw;
                    pl[off] = lw;
                }
            } else {
                *(float2*)(Out + (size_t)r0 * CC + cg) = lo;
                *(float2*)(Out + (size_t)r1 * CC + cg) = hi;
            }
        }
    }
}

// ---------------------------------------------------------------------------
// Flash attention on mma.sync.
// QK^T: 3-term bf16 split. PV: single fp16 P x 2-term fp16 V (err ~2^-12).
// CTA = 64 q-rows of one (b,h), 4 warps (m16 each), Bc=64 per iteration.
// Smem planes: 64 rows x 144B (64 elems + 16B pad), conflict-free ldmatrix.
// ---------------------------------------------------------------------------
#define QPL 9216                     // 64 * 144
#define FL_STAGE (4*QPL)             // Kh,Kl,Vh,Vl
#define FL_SMEM_BYTES (2*QPL + 2*FL_STAGE)   // 92160

__global__ __launch_bounds__(128)
void flash_mma_kernel()
{
    extern __shared__ __align__(128) char smem[];
    const uint32_t sb = smem_to_u32(smem);
    const int tid = threadIdx.x, lane = tid & 31, wid = tid >> 5;
    const int qt = (int)gridDim.x - 1 - (int)blockIdx.x;   // heavy tiles first
    const int bh = blockIdx.y;
    const size_t base = (size_t)bh * TT * DH;

    // Q planes -> smem (part of cp.async group 0)
    {
        const __nv_bfloat16* q0 = g_qh + base + (size_t)qt * 64 * DH;
        const __nv_bfloat16* q1 = g_ql + base + (size_t)qt * 64 * DH;
        #pragma unroll
        for (int i = 0; i < 4; i++) {
            const int ch = tid + i * 128;        // 0..511
            const int r = ch >> 3, c = ch & 7;
            cp16(sb +       r*144 + c*16, q0 + r*DH + c*8);
            cp16(sb + QPL + r*144 + c*16, q1 + r*DH + c*8);
        }
    }
    const __nv_bfloat16* kh = g_kh + base;
    const __nv_bfloat16* kl = g_kl + base;
    const __half* vh = g_vh + base;
    const __half* vl = g_vl + base;

    auto issue_kv = [&](int jc, int st) {
        const uint32_t d0 = sb + 2*QPL + st*FL_STAGE;
        const size_t g0 = (size_t)jc * 64 * DH;
        #pragma unroll
        for (int i = 0; i < 4; i++) {
            const int ch = tid + i * 128;
            const int r = ch >> 3, c = ch & 7;
            const uint32_t so = r*144 + c*16;
            const size_t go = g0 + (size_t)r*DH + c*8;
            cp16(d0 +         so, kh + go);
            cp16(d0 +   QPL + so, kl + go);
            cp16(d0 + 2*QPL + so, vh + go);
            cp16(d0 + 3*QPL + so, vl + go);
        }
        asm volatile("cp.async.commit_group;" ::: "memory");
    };

    issue_kv(0, 0);   // group 0 (includes Q)

    uint32_t qfh[4][4], qfl[4][4];
    float oacc[8][4];
    #pragma unroll
    for (int nt = 0; nt < 8; nt++)
        #pragma unroll
        for (int e = 0; e < 4; e++) oacc[nt][e] = 0.f;
    float m0 = -INFINITY, m1 = -INFINITY, l0 = 0.f, l1 = 0.f;

    const int rsel = lane & 15;
    const uint32_t chalf = 16 * (lane >> 4);
    const int vrow = (lane & 7) + 8 * ((lane >> 4) & 1);
    const uint32_t vcol = 16 * ((lane >> 3) & 1);

    for (int jc = 0; jc <= qt; jc++) {
        if (jc < qt) {
            issue_kv(jc + 1, (jc + 1) & 1);
            asm volatile("cp.async.wait_group 1;" ::: "memory");
        } else {
            asm volatile("cp.async.wait_group 0;" ::: "memory");
        }
        __syncthreads();

        if (jc == 0) {   // Q fragments once
            #pragma unroll
            for (int ku = 0; ku < 4; ku++) {
                const uint32_t qa = sb + (uint32_t)((wid << 4) + rsel)*144 + ku*32 + chalf;
                ldm_x4(qfh[ku], qa);
                ldm_x4(qfl[ku], qa + QPL);
            }
        }

        const uint32_t s0 = sb + 2*QPL + (jc & 1)*FL_STAGE;

        // ---- S = Q @ K^T (3-term split) ----
        float s[8][4];
        #pragma unroll
        for (int nt = 0; nt < 8; nt++)
            #pragma unroll
            for (int e = 0; e < 4; e++) s[nt][e] = 0.f;

        #pragma unroll
        for (int ku = 0; ku < 4; ku++) {
            #pragma unroll
            for (int ng = 0; ng < 4; ng++) {
                uint32_t kh4[4], kl4[4];
                const uint32_t ka = s0 + (uint32_t)(ng*16 + rsel)*144 + ku*32 + chalf;
                ldm_x4(kh4, ka);
                ldm_x4(kl4, ka + QPL);
                mma_bf16(s[ng*2],   qfh[ku], kh4[0], kh4[2]);
                mma_bf16(s[ng*2+1], qfh[ku], kh4[1], kh4[3]);
                mma_bf16(s[ng*2],   qfh[ku], kl4[0], kl4[2]);
                mma_bf16(s[ng*2+1], qfh[ku], kl4[1], kl4[3]);
                mma_bf16(s[ng*2],   qfl[ku], kh4[0], kh4[2]);
                mma_bf16(s[ng*2+1], qfl[ku], kh4[1], kh4[3]);
            }
        }

        // ---- scale + causal mask ----
        #pragma unroll
        for (int nt = 0; nt < 8; nt++)
            #pragma unroll
            for (int e = 0; e < 4; e++) s[nt][e] *= 0.125f;
        if (jc == qt) {
            const int r0l = (wid << 4) + (lane >> 2);
            const int cb  = (lane & 3) * 2;
            #pragma unroll
            for (int nt = 0; nt < 8; nt++) {
                const int c0 = nt*8 + cb;
                if (c0     > r0l    ) s[nt][0] = -INFINITY;
                if (c0 + 1 > r0l    ) s[nt][1] = -INFINITY;
                if (c0     > r0l + 8) s[nt][2] = -INFINITY;
                if (c0 + 1 > r0l + 8) s[nt][3] = -INFINITY;
            }
        }

        // ---- online softmax (rows g and g+8; row on 4 lanes) ----
        float mx0 = -INFINITY, mx1 = -INFINITY;
        #pragma unroll
        for (int nt = 0; nt < 8; nt++) {
            mx0 = fmaxf(mx0, fmaxf(s[nt][0], s[nt][1]));
            mx1 = fmaxf(mx1, fmaxf(s[nt][2], s[nt][3]));
        }
        mx0 = fmaxf(mx0, __shfl_xor_sync(0xffffffffu, mx0, 1));
        mx0 = fmaxf(mx0, __shfl_xor_sync(0xffffffffu, mx0, 2));
        mx1 = fmaxf(mx1, __shfl_xor_sync(0xffffffffu, mx1, 1));
        mx1 = fmaxf(mx1, __shfl_xor_sync(0xffffffffu, mx1, 2));
        const float mn0 = fmaxf(m0, mx0), mn1 = fmaxf(m1, mx1);
        const float a0 = __expf(m0 - mn0), a1 = __expf(m1 - mn1);
        float sum0 = 0.f, sum1 = 0.f;
        #pragma unroll
        for (int nt = 0; nt < 8; nt++) {
            s[nt][0] = __expf(s[nt][0] - mn0); sum0 += s[nt][0];
            s[nt][1] = __expf(s[nt][1] - mn0); sum0 += s[nt][1];
            s[nt][2] = __expf(s[nt][2] - mn1); sum1 += s[nt][2];
            s[nt][3] = __expf(s[nt][3] - mn1); sum1 += s[nt][3];
        }
        sum0 += __shfl_xor_sync(0xffffffffu, sum0, 1);
        sum0 += __shfl_xor_sync(0xffffffffu, sum0, 2);
        sum1 += __shfl_xor_sync(0xffffffffu, sum1, 1);
        sum1 += __shfl_xor_sync(0xffffffffu, sum1, 2);
        l0 = l0 * a0 + sum0;  m0 = mn0;
        l1 = l1 * a1 + sum1;  m1 = mn1;
        #pragma unroll
        for (int nt = 0; nt < 8; nt++) {
            oacc[nt][0] *= a0; oacc[nt][1] *= a0;
            oacc[nt][2] *= a1; oacc[nt][3] *= a1;
        }

        // ---- O += P @ V (single fp16 P, 2-term fp16 V) ----
        #pragma unroll
        for (int u = 0; u < 4; u++) {
            uint32_t pa[4];
            #pragma unroll
            for (int t = 0; t < 4; t++) {
                const int j = 2*u + (t >> 1);
                const int e0 = (t & 1) * 2;
                pa[t] = pack_hf(s[j][e0], s[j][e0 + 1]);
            }
            #pragma unroll
            for (int dg = 0; dg < 4; dg++) {
                uint32_t vh4[4], vl4[4];
                const uint32_t va = s0 + 2*QPL + (uint32_t)(u*16 + vrow)*144 + dg*32 + vcol;
                ldm_x4_t(vh4, va);
                ldm_x4_t(vl4, va + QPL);
                mma_f16(oacc[dg*2],   pa, vh4[0], vh4[2]);
                mma_f16(oacc[dg*2+1], pa, vh4[1], vh4[3]);
                mma_f16(oacc[dg*2],   pa, vl4[0], vl4[2]);
                mma_f16(oacc[dg*2+1], pa, vl4[1], vl4[3]);
            }
        }
        __syncthreads();   // stage reads done before refill
    }

    // ---- normalize + write y [B,T,C] fp32 ----
    const int g  = lane >> 2;
    const int t2 = (lane & 3) * 2;
    const int bb = bh >> 4, hh = bh & (NH - 1);
    const int row0 = qt*64 + (wid << 4) + g;
    const float inv0 = 1.0f / l0, inv1 = 1.0f / l1;
    float* y0 = g_y + ((size_t)bb*TT + row0)*CC + hh*DH;
    float* y1 = g_y + ((size_t)bb*TT + row0 + 8)*CC + hh*DH;
    #pragma unroll
    for (int nt = 0; nt < 8; nt++) {
        *(float2*)(y0 + nt*8 + t2) = make_float2(oacc[nt][0]*inv0, oacc[nt][1]*inv0);
        *(float2*)(y1 + nt*8 + t2) = make_float2(oacc[nt][2]*inv1, oacc[nt][3]*inv1);
    }
}

// ---------------------------------------------------------------------------
extern "C" void kernel_launch(void* const* d_in, const int* in_sizes, int n_in,
                              void* d_out, int out_size)
{
    (void)in_sizes; (void)n_in; (void)out_size;
    const float* x     = (const float*)d_in[0];
    const float* Wqkv  = (const float*)d_in[1];
    const float* bqkv  = (const float*)d_in[2];
    const float* Wproj = (const float*)d_in[3];
    const float* bproj = (const float*)d_in[4];
    float* out = (float*)d_out;

    static bool attr_set = false;
    if (!attr_set) {
        cudaFuncSetAttribute(flash_mma_kernel,
            cudaFuncAttributeMaxDynamicSharedMemorySize, FL_SMEM_BYTES);
        cudaFuncSetAttribute(mma_gemm_kernel<0>,
            cudaFuncAttributeMaxDynamicSharedMemorySize, GEMM_SMEM_BYTES);
        cudaFuncSetAttribute(mma_gemm_kernel<1>,
            cudaFuncAttributeMaxDynamicSharedMemorySize, GEMM_SMEM_BYTES);
        attr_set = true;
    }

    const int act4 = (MROWS * KDIM) / 4;

    // 0) splits: x -> g_xa ; Wqkv -> g_wq ; Wproj -> g_wp
    conv_act<0><<<act4 / 256, 256>>>(x);
    conv_w_kernel<3072><<<dim3(KDIM/32, 3072/32), dim3(32, 8)>>>(Wqkv);
    conv_w_kernel<1024><<<dim3(KDIM/32, 1024/32), dim3(32, 8)>>>(Wproj);

    // 1) QKV projection -> split q/k (bf16), v (fp16), [B,H,T,D]
    mma_gemm_kernel<0><<<dim3(3072/128, MROWS/128), 256, GEMM_SMEM_BYTES>>>(bqkv, nullptr);

    // 2) causal flash attention (tensor cores) -> g_y [B,T,C]
    flash_mma_kernel<<<dim3(TT/64, NB*NH), 128, FL_SMEM_BYTES>>>();

    // 3) y split + output projection -> d_out
    conv_act<1><<<act4 / 256, 256>>>(nullptr);
    mma_gemm_kernel<1><<<dim3(1024/128, MROWS/128), 256, GEMM_SMEM_BYTES>>>(bproj, out);
}